// round 3
// baseline (speedup 1.0000x reference)
#include <cuda_runtime.h>
#include <stdint.h>

#define N_NODES 50000
#define N_EDGES 800000

// ---------------- scratch (allocation-free: __device__ globals) ----------------
__device__ __align__(16) float g_dinv[N_NODES];
__device__ __align__(16) float g_h[N_NODES * 128];   // GEMM output / gather source
__device__ __align__(16) float g_o[N_NODES * 128];   // scatter accumulator (layers 1,2)
__device__ int g_row[N_EDGES];
__device__ int g_col[N_EDGES];
__device__ int g_is64;

// ---------------- edge-index dtype detection + decode ----------------
// If edge_index is int64 (values < 50000), every odd int32 word of the raw
// buffer is 0. If int32, odd words are random indices (all-zero prob ~ 0).
__global__ void detect_kernel(const int* __restrict__ ei_raw) {
    __shared__ int any;
    if (threadIdx.x == 0) any = 0;
    __syncthreads();
    int nz = 0;
    for (int i = threadIdx.x; i < 1024; i += blockDim.x)
        nz |= ei_raw[2 * i + 1];
    if (nz) atomicOr(&any, 1);
    __syncthreads();
    if (threadIdx.x == 0) g_is64 = (any == 0);
}

__global__ void decode_kernel(const int* __restrict__ ei_raw) {
    int i = blockIdx.x * blockDim.x + threadIdx.x;
    if (i >= N_EDGES) return;
    if (g_is64) {
        g_row[i] = ei_raw[2 * i];
        g_col[i] = ei_raw[2 * (N_EDGES + i)];
    } else {
        g_row[i] = ei_raw[i];
        g_col[i] = ei_raw[N_EDGES + i];
    }
}

// ---------------- degree / normalization ----------------
__global__ void deg_init_kernel() {
    int i = blockIdx.x * blockDim.x + threadIdx.x;
    if (i < N_NODES) g_dinv[i] = 1.0f;  // self-loop
}

__global__ void deg_count_kernel() {
    int i = blockIdx.x * blockDim.x + threadIdx.x;
    if (i < N_EDGES) atomicAdd(&g_dinv[g_col[i]], 1.0f);
}

__global__ void dinv_kernel() {
    int i = blockIdx.x * blockDim.x + threadIdx.x;
    if (i < N_NODES) g_dinv[i] = rsqrtf(g_dinv[i]);   // deg >= 1 (self-loop)
}

// ---------------- tiled SIMT GEMM: C[M,N] = A[M,K] * B[K,N] ----------------
#define BM 64
#define BN 64
#define BK 16
#define TM 4
#define TN 4

__device__ __forceinline__ void gemm_body(
    const float* __restrict__ A, const float* __restrict__ B,
    float* __restrict__ C, int N, int K)
{
    __shared__ float As[BK][BM + 4];
    __shared__ float Bs[BK][BN];

    int tx = threadIdx.x & 15;
    int ty = threadIdx.x >> 4;
    int rowBase = blockIdx.y * BM;
    int colBase = blockIdx.x * BN;

    float acc[TM][TN];
#pragma unroll
    for (int i = 0; i < TM; i++)
#pragma unroll
        for (int j = 0; j < TN; j++) acc[i][j] = 0.0f;

    for (int k0 = 0; k0 < K; k0 += BK) {
#pragma unroll
        for (int i = threadIdx.x; i < BM * BK; i += 256) {
            int m = i >> 4;          // /BK
            int k = i & 15;          // %BK
            int gm = rowBase + m;
            As[k][m] = (gm < N_NODES) ? A[(size_t)gm * K + k0 + k] : 0.0f;
        }
#pragma unroll
        for (int i = threadIdx.x; i < BK * BN; i += 256) {
            int k = i >> 6;          // /BN
            int n = i & 63;          // %BN
            Bs[k][n] = B[(size_t)(k0 + k) * N + colBase + n];
        }
        __syncthreads();

#pragma unroll
        for (int k = 0; k < BK; k++) {
            float a[TM], b[TN];
#pragma unroll
            for (int i = 0; i < TM; i++) a[i] = As[k][ty * TM + i];
#pragma unroll
            for (int j = 0; j < TN; j++) b[j] = Bs[k][tx * TN + j];
#pragma unroll
            for (int i = 0; i < TM; i++)
#pragma unroll
                for (int j = 0; j < TN; j++) acc[i][j] += a[i] * b[j];
        }
        __syncthreads();
    }

#pragma unroll
    for (int i = 0; i < TM; i++) {
        int gm = rowBase + ty * TM + i;
        if (gm >= N_NODES) continue;
        float* crow = C + (size_t)gm * N + colBase + tx * TN;
#pragma unroll
        for (int j = 0; j < TN; j++) crow[j] = acc[i][j];
    }
}

// A = external x, C = g_h
__global__ __launch_bounds__(256) void gemm_xh_kernel(
    const float* __restrict__ A, const float* __restrict__ B, int N, int K)
{
    gemm_body(A, B, g_h, N, K);
}

// A = g_o, C = g_h
__global__ __launch_bounds__(256) void gemm_oh_kernel(
    const float* __restrict__ B, int N, int K)
{
    gemm_body(g_o, B, g_h, N, K);
}

// ---------------- self-loop init + bias: dst[v][:] = dinv[v]^2 * h[v][:] + b ----------------
template <int DIM>
__device__ __forceinline__ void selfinit_body(float* __restrict__ dst,
                                              const float* __restrict__ b)
{
    int idx = blockIdx.x * blockDim.x + threadIdx.x;   // over N_NODES*DIM/4
    if (idx >= N_NODES * (DIM / 4)) return;
    int v = idx / (DIM / 4);
    int j = idx % (DIM / 4);
    float d = g_dinv[v];
    float w = d * d;
    float4 val = ((const float4*)g_h)[idx];
    float4 bb = ((const float4*)b)[j];
    val.x = val.x * w + bb.x;
    val.y = val.y * w + bb.y;
    val.z = val.z * w + bb.z;
    val.w = val.w * w + bb.w;
    ((float4*)dst)[idx] = val;
}

template <int DIM>
__global__ void selfinit_o_kernel(const float* __restrict__ b) { selfinit_body<DIM>(g_o, b); }

template <int DIM>
__global__ void selfinit_out_kernel(float* __restrict__ out, const float* __restrict__ b)
{ selfinit_body<DIM>(out, b); }

// ---------------- edge scatter: dst[col] += dinv[row]*dinv[col] * h[row] ----------------
template <int DIM>
__device__ __forceinline__ void scatter_body(float* __restrict__ dst)
{
    constexpr int L = DIM / 4;  // lanes per edge (32 or 16)
    int gid = blockIdx.x * blockDim.x + threadIdx.x;
    int e = gid / L;
    int j = gid % L;
    if (e >= N_EDGES) return;

    int r = g_row[e];
    int c = g_col[e];
    float w = g_dinv[r] * g_dinv[c];

    float4 v = ((const float4*)(g_h + (size_t)r * DIM))[j];
    v.x *= w; v.y *= w; v.z *= w; v.w *= w;

    float* p = dst + (size_t)c * DIM + 4 * j;
    asm volatile("red.global.add.v4.f32 [%0], {%1, %2, %3, %4};"
                 :: "l"(p), "f"(v.x), "f"(v.y), "f"(v.z), "f"(v.w)
                 : "memory");
}

template <int DIM>
__global__ void scatter_o_kernel() { scatter_body<DIM>(g_o); }

template <int DIM>
__global__ void scatter_out_kernel(float* __restrict__ out) { scatter_body<DIM>(out); }

// ---------------- relu (bias already folded into selfinit) ----------------
__global__ void relu_o_kernel(int n4)
{
    int idx = blockIdx.x * blockDim.x + threadIdx.x;
    if (idx >= n4) return;
    float4 v = ((const float4*)g_o)[idx];
    v.x = fmaxf(v.x, 0.0f);
    v.y = fmaxf(v.y, 0.0f);
    v.z = fmaxf(v.z, 0.0f);
    v.w = fmaxf(v.w, 0.0f);
    ((float4*)g_o)[idx] = v;
}

// ---------------- launch ----------------
extern "C" void kernel_launch(void* const* d_in, const int* in_sizes, int n_in,
                              void* d_out, int out_size)
{
    const float* x      = (const float*)d_in[0];
    const int*   ei_raw = (const int*)d_in[1];
    const float* W1 = (const float*)d_in[2];
    const float* b1 = (const float*)d_in[3];
    const float* W2 = (const float*)d_in[4];
    const float* b2 = (const float*)d_in[5];
    const float* W3 = (const float*)d_in[6];
    const float* b3 = (const float*)d_in[7];
    float* out = (float*)d_out;

    // edge decode (dtype-robust) + normalization coefficients
    detect_kernel<<<1, 256>>>(ei_raw);
    decode_kernel<<<(N_EDGES + 255) / 256, 256>>>(ei_raw);
    deg_init_kernel<<<(N_NODES + 255) / 256, 256>>>();
    deg_count_kernel<<<(N_EDGES + 255) / 256, 256>>>();
    dinv_kernel<<<(N_NODES + 255) / 256, 256>>>();

    const int gridRows = (N_NODES + BM - 1) / BM;   // 782
    const int si128 = (N_NODES * 32 + 255) / 256;
    const int si64  = (N_NODES * 16 + 255) / 256;
    const int sc128 = (N_EDGES * 32 + 255) / 256;
    const int sc64  = (N_EDGES * 16 + 255) / 256;
    const int rl128 = (N_NODES * 32 + 255) / 256;

    // ---- layer 1: h = x @ W1 ; o = b1 + scatter(h) ; o = relu(o) ----
    gemm_xh_kernel<<<dim3(128 / BN, gridRows), 256>>>(x, W1, 128, 128);
    selfinit_o_kernel<128><<<si128, 256>>>(b1);
    scatter_o_kernel<128><<<sc128, 256>>>();
    relu_o_kernel<<<rl128, 256>>>(N_NODES * 32);

    // ---- layer 2 ----
    gemm_oh_kernel<<<dim3(128 / BN, gridRows), 256>>>(W2, 128, 128);
    selfinit_o_kernel<128><<<si128, 256>>>(b2);
    scatter_o_kernel<128><<<sc128, 256>>>();
    relu_o_kernel<<<rl128, 256>>>(N_NODES * 32);

    // ---- layer 3 (out dim 64 -> d_out, no relu) ----
    gemm_oh_kernel<<<dim3(64 / BN, gridRows), 256>>>(W3, 64, 128);
    selfinit_out_kernel<64><<<si64, 256>>>(out, b3);
    scatter_out_kernel<64><<<sc64, 256>>>(out);
}

// round 5
// speedup vs baseline: 1.1556x; 1.1556x over previous
#include <cuda_runtime.h>
#include <stdint.h>

#define N_NODES 50000
#define N_EDGES 800000

// ---------------- scratch (allocation-free: __device__ globals) ----------------
__device__ __align__(16) float g_dinv[N_NODES];
__device__ __align__(16) float g_h[N_NODES * 128];   // GEMM output, pre-scaled by dinv[row]
__device__ __align__(16) float g_o[N_NODES * 128];   // layer output
__device__ int g_row[N_EDGES];
__device__ int g_col[N_EDGES];
__device__ int g_adj[N_EDGES];        // CSR: source nodes grouped by dest
__device__ int g_off[N_NODES + 1];    // CSR offsets
__device__ int g_cur[N_NODES];        // fill cursors
__device__ int g_degi[N_NODES];       // in-degree (edges only)
__device__ int g_is64;

// ---------------- edge-index dtype detection + decode ----------------
__global__ void detect_kernel(const int* __restrict__ ei_raw) {
    __shared__ int any;
    if (threadIdx.x == 0) any = 0;
    __syncthreads();
    int nz = 0;
    for (int i = threadIdx.x; i < 1024; i += blockDim.x)
        nz |= ei_raw[2 * i + 1];
    if (nz) atomicOr(&any, 1);
    __syncthreads();
    if (threadIdx.x == 0) g_is64 = (any == 0);
}

__global__ void decode_kernel(const int* __restrict__ ei_raw) {
    int i = blockIdx.x * blockDim.x + threadIdx.x;
    if (i >= N_EDGES) return;
    if (g_is64) {
        g_row[i] = ei_raw[2 * i];
        g_col[i] = ei_raw[2 * (N_EDGES + i)];
    } else {
        g_row[i] = ei_raw[i];
        g_col[i] = ei_raw[N_EDGES + i];
    }
    if (i < N_NODES) g_degi[i] = 0;
}

__global__ void deg_count_kernel() {
    int i = blockIdx.x * blockDim.x + threadIdx.x;
    if (i < N_EDGES) atomicAdd(&g_degi[g_col[i]], 1);
}

// ---------------- single-block exclusive scan over degrees + dinv ----------------
__global__ __launch_bounds__(1024) void scan_kernel() {
    __shared__ int part[1024];
    const int C = (N_NODES + 1023) / 1024;   // 49
    int t = threadIdx.x;
    int base = t * C;
    int s = 0;
    for (int i = 0; i < C; i++) {
        int v = base + i;
        if (v < N_NODES) s += g_degi[v];
    }
    part[t] = s;
    __syncthreads();
    for (int off = 1; off < 1024; off <<= 1) {
        int v = part[t];
        int add = (t >= off) ? part[t - off] : 0;
        __syncthreads();
        part[t] = v + add;
        __syncthreads();
    }
    int run = (t > 0) ? part[t - 1] : 0;
    for (int i = 0; i < C; i++) {
        int v = base + i;
        if (v < N_NODES) {
            g_off[v] = run;
            g_cur[v] = run;
            int d = g_degi[v];
            run += d;
            g_dinv[v] = rsqrtf((float)(1 + d));   // +1 self-loop
        }
    }
    if (t == 1023) g_off[N_NODES] = run;
}

__global__ void fill_kernel() {
    int i = blockIdx.x * blockDim.x + threadIdx.x;
    if (i >= N_EDGES) return;
    int c = g_col[i];
    int pos = atomicAdd(&g_cur[c], 1);
    g_adj[pos] = g_row[i];
}

// ---------------- tiled SIMT GEMM: g_h[m,:] = dinv[m] * (A @ B)[m,:] ----------------
#define BM 64
#define BN 64
#define BK 16
#define TM 4
#define TN 4

__device__ __forceinline__ void gemm_body(
    const float* __restrict__ A, const float* __restrict__ B, int N, int K)
{
    __shared__ float As[BK][BM + 4];
    __shared__ float Bs[BK][BN];

    int tx = threadIdx.x & 15;
    int ty = threadIdx.x >> 4;
    int rowBase = blockIdx.y * BM;
    int colBase = blockIdx.x * BN;

    float acc[TM][TN];
#pragma unroll
    for (int i = 0; i < TM; i++)
#pragma unroll
        for (int j = 0; j < TN; j++) acc[i][j] = 0.0f;

    for (int k0 = 0; k0 < K; k0 += BK) {
#pragma unroll
        for (int i = threadIdx.x; i < BM * BK; i += 256) {
            int m = i >> 4;
            int k = i & 15;
            int gm = rowBase + m;
            As[k][m] = (gm < N_NODES) ? A[(size_t)gm * K + k0 + k] : 0.0f;
        }
#pragma unroll
        for (int i = threadIdx.x; i < BK * BN; i += 256) {
            int k = i >> 6;
            int n = i & 63;
            Bs[k][n] = B[(size_t)(k0 + k) * N + colBase + n];
        }
        __syncthreads();

#pragma unroll
        for (int k = 0; k < BK; k++) {
            float a[TM], b[TN];
#pragma unroll
            for (int i = 0; i < TM; i++) a[i] = As[k][ty * TM + i];
#pragma unroll
            for (int j = 0; j < TN; j++) b[j] = Bs[k][tx * TN + j];
#pragma unroll
            for (int i = 0; i < TM; i++)
#pragma unroll
                for (int j = 0; j < TN; j++) acc[i][j] += a[i] * b[j];
        }
        __syncthreads();
    }

#pragma unroll
    for (int i = 0; i < TM; i++) {
        int gm = rowBase + ty * TM + i;
        if (gm >= N_NODES) continue;
        float dm = g_dinv[gm];                       // pre-scale rows by dinv
        float* crow = g_h + (size_t)gm * N + colBase + tx * TN;
#pragma unroll
        for (int j = 0; j < TN; j++) crow[j] = acc[i][j] * dm;
    }
}

__global__ __launch_bounds__(256) void gemm_xh_kernel(
    const float* __restrict__ A, const float* __restrict__ B, int N, int K)
{
    gemm_body(A, B, N, K);
}

__global__ __launch_bounds__(256) void gemm_oh_kernel(
    const float* __restrict__ B, int N, int K)
{
    gemm_body(g_o, B, N, K);
}

// ---------------- CSR aggregate (warp per node), DIM=128, float4 lanes ----------------
// out[c] = relu?( dinv[c] * (hs[c] + sum_{r in adj[c]} hs[r]) + b )
template <bool RELU>
__global__ __launch_bounds__(256) void agg128_kernel(const float* __restrict__ b)
{
    int warp = (blockIdx.x * blockDim.x + threadIdx.x) >> 5;
    int lane = threadIdx.x & 31;
    if (warp >= N_NODES) return;
    int c = warp;

    const float4* hs = (const float4*)g_h;
    float4 acc = hs[(size_t)c * 32 + lane];          // self-loop term

    int s = g_off[c], e = g_off[c + 1];
    int i = s;
    for (; i + 4 <= e; i += 4) {
        int r0 = g_adj[i], r1 = g_adj[i + 1], r2 = g_adj[i + 2], r3 = g_adj[i + 3];
        float4 v0 = hs[(size_t)r0 * 32 + lane];
        float4 v1 = hs[(size_t)r1 * 32 + lane];
        float4 v2 = hs[(size_t)r2 * 32 + lane];
        float4 v3 = hs[(size_t)r3 * 32 + lane];
        acc.x += (v0.x + v1.x) + (v2.x + v3.x);
        acc.y += (v0.y + v1.y) + (v2.y + v3.y);
        acc.z += (v0.z + v1.z) + (v2.z + v3.z);
        acc.w += (v0.w + v1.w) + (v2.w + v3.w);
    }
    for (; i < e; i++) {
        float4 v = hs[(size_t)g_adj[i] * 32 + lane];
        acc.x += v.x; acc.y += v.y; acc.z += v.z; acc.w += v.w;
    }

    float d = g_dinv[c];
    float4 bb = ((const float4*)b)[lane];
    acc.x = acc.x * d + bb.x;
    acc.y = acc.y * d + bb.y;
    acc.z = acc.z * d + bb.z;
    acc.w = acc.w * d + bb.w;
    if (RELU) {
        acc.x = fmaxf(acc.x, 0.0f); acc.y = fmaxf(acc.y, 0.0f);
        acc.z = fmaxf(acc.z, 0.0f); acc.w = fmaxf(acc.w, 0.0f);
    }
    ((float4*)g_o)[(size_t)c * 32 + lane] = acc;
}

// DIM=64 final layer: float2 lanes, writes d_out, no relu
__global__ __launch_bounds__(256) void agg64_kernel(float* __restrict__ out,
                                                    const float* __restrict__ b)
{
    int warp = (blockIdx.x * blockDim.x + threadIdx.x) >> 5;
    int lane = threadIdx.x & 31;
    if (warp >= N_NODES) return;
    int c = warp;

    const float2* hs = (const float2*)g_h;
    float2 acc = hs[(size_t)c * 32 + lane];

    int s = g_off[c], e = g_off[c + 1];
    int i = s;
    for (; i + 4 <= e; i += 4) {
        int r0 = g_adj[i], r1 = g_adj[i + 1], r2 = g_adj[i + 2], r3 = g_adj[i + 3];
        float2 v0 = hs[(size_t)r0 * 32 + lane];
        float2 v1 = hs[(size_t)r1 * 32 + lane];
        float2 v2 = hs[(size_t)r2 * 32 + lane];
        float2 v3 = hs[(size_t)r3 * 32 + lane];
        acc.x += (v0.x + v1.x) + (v2.x + v3.x);
        acc.y += (v0.y + v1.y) + (v2.y + v3.y);
    }
    for (; i < e; i++) {
        float2 v = hs[(size_t)g_adj[i] * 32 + lane];
        acc.x += v.x; acc.y += v.y;
    }

    float d = g_dinv[c];
    float2 bb = ((const float2*)b)[lane];
    acc.x = acc.x * d + bb.x;
    acc.y = acc.y * d + bb.y;
    ((float2*)out)[(size_t)c * 32 + lane] = acc;
}

// ---------------- launch ----------------
extern "C" void kernel_launch(void* const* d_in, const int* in_sizes, int n_in,
                              void* d_out, int out_size)
{
    const float* x      = (const float*)d_in[0];
    const int*   ei_raw = (const int*)d_in[1];
    const float* W1 = (const float*)d_in[2];
    const float* b1 = (const float*)d_in[3];
    const float* W2 = (const float*)d_in[4];
    const float* b2 = (const float*)d_in[5];
    const float* W3 = (const float*)d_in[6];
    const float* b3 = (const float*)d_in[7];
    float* out = (float*)d_out;

    // ---- CSR build + normalization (per call; inputs may change) ----
    detect_kernel<<<1, 256>>>(ei_raw);
    decode_kernel<<<(N_EDGES + 255) / 256, 256>>>(ei_raw);
    deg_count_kernel<<<(N_EDGES + 255) / 256, 256>>>();
    scan_kernel<<<1, 1024>>>();
    fill_kernel<<<(N_EDGES + 255) / 256, 256>>>();

    const int gridRows = (N_NODES + BM - 1) / BM;          // 782
    const int aggGrid  = (N_NODES * 32 + 255) / 256;       // warp per node

    // ---- layer 1 ----
    gemm_xh_kernel<<<dim3(128 / BN, gridRows), 256>>>(x, W1, 128, 128);
    agg128_kernel<true><<<aggGrid, 256>>>(b1);

    // ---- layer 2 ----
    gemm_oh_kernel<<<dim3(128 / BN, gridRows), 256>>>(W2, 128, 128);
    agg128_kernel<true><<<aggGrid, 256>>>(b2);

    // ---- layer 3 (dim 64 -> d_out) ----
    gemm_oh_kernel<<<dim3(64 / BN, gridRows), 256>>>(W3, 64, 128);
    agg64_kernel<<<aggGrid, 256>>>(out, b3);
}

// round 6
// speedup vs baseline: 1.5281x; 1.3224x over previous
#include <cuda_runtime.h>
#include <stdint.h>

#define N_NODES 50000
#define N_EDGES 800000
#define NB      208            // scan blocks: 208*256 = 53248 >= N_NODES

// ---------------- scratch (allocation-free: __device__ globals) ----------------
__device__ __align__(16) float g_dinv[N_NODES];
__device__ __align__(16) float g_h[N_NODES * 128];   // GEMM output, pre-scaled by dinv[row]
__device__ __align__(16) float g_o[N_NODES * 128];   // layer output
__device__ int g_row[N_EDGES];
__device__ int g_col[N_EDGES];
__device__ int g_adj[N_EDGES];        // CSR: source nodes grouped by dest
__device__ int g_off[N_NODES + 1];    // CSR offsets
__device__ int g_cur[N_NODES];        // fill cursors
__device__ int g_degi[N_NODES];       // in-degree (edges only)
__device__ int g_bsum[NB];            // per-block degree sums
__device__ int g_bpref[NB];           // exclusive prefix of block sums
__device__ int g_is64;

// ---------------- edge-index dtype detection ----------------
__global__ void detect_kernel(const int* __restrict__ ei_raw) {
    __shared__ int any;
    if (threadIdx.x == 0) any = 0;
    __syncthreads();
    int nz = 0;
    for (int i = threadIdx.x; i < 1024; i += blockDim.x)
        nz |= ei_raw[2 * i + 1];
    if (nz) atomicOr(&any, 1);
    __syncthreads();
    if (threadIdx.x == 0) g_is64 = (any == 0);
}

__global__ void zero_deg_kernel() {
    int i = blockIdx.x * blockDim.x + threadIdx.x;
    if (i < N_NODES) g_degi[i] = 0;
}

// decode + degree count fused (one 800K pass)
__global__ void decode_count_kernel(const int* __restrict__ ei_raw) {
    int i = blockIdx.x * blockDim.x + threadIdx.x;
    if (i >= N_EDGES) return;
    int r, c;
    if (g_is64) {
        r = ei_raw[2 * i];
        c = ei_raw[2 * (N_EDGES + i)];
    } else {
        r = ei_raw[i];
        c = ei_raw[N_EDGES + i];
    }
    g_row[i] = r;
    g_col[i] = c;
    atomicAdd(&g_degi[c], 1);
}

// ---------------- 3-phase parallel exclusive scan over degrees ----------------
__global__ __launch_bounds__(256) void scanA_kernel() {
    __shared__ int sh[256];
    int i = blockIdx.x * 256 + threadIdx.x;
    int v = (i < N_NODES) ? g_degi[i] : 0;
    sh[threadIdx.x] = v;
    __syncthreads();
    for (int o = 128; o > 0; o >>= 1) {
        if (threadIdx.x < o) sh[threadIdx.x] += sh[threadIdx.x + o];
        __syncthreads();
    }
    if (threadIdx.x == 0) g_bsum[blockIdx.x] = sh[0];
}

__global__ __launch_bounds__(256) void scanB_kernel() {
    __shared__ int sh[256];
    int t = threadIdx.x;
    int v = (t < NB) ? g_bsum[t] : 0;
    sh[t] = v;
    __syncthreads();
    for (int o = 1; o < 256; o <<= 1) {
        int x = sh[t];
        int a = (t >= o) ? sh[t - o] : 0;
        __syncthreads();
        sh[t] = x + a;
        __syncthreads();
    }
    if (t < NB) g_bpref[t] = sh[t] - v;   // exclusive
    if (t == 255) g_off[N_NODES] = sh[255];
}

__global__ __launch_bounds__(256) void scanC_kernel() {
    __shared__ int sh[256];
    int t = threadIdx.x;
    int i = blockIdx.x * 256 + t;
    int d = (i < N_NODES) ? g_degi[i] : 0;
    sh[t] = d;
    __syncthreads();
    for (int o = 1; o < 256; o <<= 1) {
        int x = sh[t];
        int a = (t >= o) ? sh[t - o] : 0;
        __syncthreads();
        sh[t] = x + a;
        __syncthreads();
    }
    if (i < N_NODES) {
        int excl = sh[t] - d + g_bpref[blockIdx.x];
        g_off[i] = excl;
        g_cur[i] = excl;
        g_dinv[i] = rsqrtf((float)(1 + d));   // +1 self-loop
    }
}

__global__ void fill_kernel() {
    int i = blockIdx.x * blockDim.x + threadIdx.x;
    if (i >= N_EDGES) return;
    int c = g_col[i];
    int pos = atomicAdd(&g_cur[c], 1);
    g_adj[pos] = g_row[i];
}

// ---------------- tiled SIMT GEMM: g_h[m,:] = dinv[m] * (A @ B)[m,:] ----------------
#define BM 64
#define BN 64
#define BK 16
#define TM 4
#define TN 4

__device__ __forceinline__ void gemm_body(
    const float* __restrict__ A, const float* __restrict__ B, int N, int K)
{
    __shared__ float As[BK][BM + 4];
    __shared__ float Bs[BK][BN];

    int tx = threadIdx.x & 15;
    int ty = threadIdx.x >> 4;
    int rowBase = blockIdx.y * BM;
    int colBase = blockIdx.x * BN;

    float acc[TM][TN];
#pragma unroll
    for (int i = 0; i < TM; i++)
#pragma unroll
        for (int j = 0; j < TN; j++) acc[i][j] = 0.0f;

    for (int k0 = 0; k0 < K; k0 += BK) {
#pragma unroll
        for (int i = threadIdx.x; i < BM * BK; i += 256) {
            int m = i >> 4;
            int k = i & 15;
            int gm = rowBase + m;
            As[k][m] = (gm < N_NODES) ? A[(size_t)gm * K + k0 + k] : 0.0f;
        }
#pragma unroll
        for (int i = threadIdx.x; i < BK * BN; i += 256) {
            int k = i >> 6;
            int n = i & 63;
            Bs[k][n] = B[(size_t)(k0 + k) * N + colBase + n];
        }
        __syncthreads();

#pragma unroll
        for (int k = 0; k < BK; k++) {
            float a[TM], b[TN];
#pragma unroll
            for (int i = 0; i < TM; i++) a[i] = As[k][ty * TM + i];
#pragma unroll
            for (int j = 0; j < TN; j++) b[j] = Bs[k][tx * TN + j];
#pragma unroll
            for (int i = 0; i < TM; i++)
#pragma unroll
                for (int j = 0; j < TN; j++) acc[i][j] += a[i] * b[j];
        }
        __syncthreads();
    }

#pragma unroll
    for (int i = 0; i < TM; i++) {
        int gm = rowBase + ty * TM + i;
        if (gm >= N_NODES) continue;
        float dm = g_dinv[gm];                       // pre-scale rows by dinv
        float* crow = g_h + (size_t)gm * N + colBase + tx * TN;
#pragma unroll
        for (int j = 0; j < TN; j++) crow[j] = acc[i][j] * dm;
    }
}

__global__ __launch_bounds__(256) void gemm_xh_kernel(
    const float* __restrict__ A, const float* __restrict__ B, int N, int K)
{
    gemm_body(A, B, N, K);
}

__global__ __launch_bounds__(256) void gemm_oh_kernel(
    const float* __restrict__ B, int N, int K)
{
    gemm_body(g_o, B, N, K);
}

// ---------------- CSR aggregate (warp per node), DIM=128, float4 lanes ----------------
// out[c] = relu?( dinv[c] * (hs[c] + sum_{r in adj[c]} hs[r]) + b )
template <bool RELU>
__global__ __launch_bounds__(256) void agg128_kernel(const float* __restrict__ b)
{
    int warp = (blockIdx.x * blockDim.x + threadIdx.x) >> 5;
    int lane = threadIdx.x & 31;
    if (warp >= N_NODES) return;
    int c = warp;

    const float4* hs = (const float4*)g_h;
    float4 acc = hs[(size_t)c * 32 + lane];          // self-loop term

    int s = g_off[c], e = g_off[c + 1];
    int i = s;
    for (; i + 4 <= e; i += 4) {
        int r0 = g_adj[i], r1 = g_adj[i + 1], r2 = g_adj[i + 2], r3 = g_adj[i + 3];
        float4 v0 = hs[(size_t)r0 * 32 + lane];
        float4 v1 = hs[(size_t)r1 * 32 + lane];
        float4 v2 = hs[(size_t)r2 * 32 + lane];
        float4 v3 = hs[(size_t)r3 * 32 + lane];
        acc.x += (v0.x + v1.x) + (v2.x + v3.x);
        acc.y += (v0.y + v1.y) + (v2.y + v3.y);
        acc.z += (v0.z + v1.z) + (v2.z + v3.z);
        acc.w += (v0.w + v1.w) + (v2.w + v3.w);
    }
    for (; i < e; i++) {
        float4 v = hs[(size_t)g_adj[i] * 32 + lane];
        acc.x += v.x; acc.y += v.y; acc.z += v.z; acc.w += v.w;
    }

    float d = g_dinv[c];
    float4 bb = ((const float4*)b)[lane];
    acc.x = acc.x * d + bb.x;
    acc.y = acc.y * d + bb.y;
    acc.z = acc.z * d + bb.z;
    acc.w = acc.w * d + bb.w;
    if (RELU) {
        acc.x = fmaxf(acc.x, 0.0f); acc.y = fmaxf(acc.y, 0.0f);
        acc.z = fmaxf(acc.z, 0.0f); acc.w = fmaxf(acc.w, 0.0f);
    }
    ((float4*)g_o)[(size_t)c * 32 + lane] = acc;
}

// DIM=64 final layer: float2 lanes, writes d_out, no relu
__global__ __launch_bounds__(256) void agg64_kernel(float* __restrict__ out,
                                                    const float* __restrict__ b)
{
    int warp = (blockIdx.x * blockDim.x + threadIdx.x) >> 5;
    int lane = threadIdx.x & 31;
    if (warp >= N_NODES) return;
    int c = warp;

    const float2* hs = (const float2*)g_h;
    float2 acc = hs[(size_t)c * 32 + lane];

    int s = g_off[c], e = g_off[c + 1];
    int i = s;
    for (; i + 4 <= e; i += 4) {
        int r0 = g_adj[i], r1 = g_adj[i + 1], r2 = g_adj[i + 2], r3 = g_adj[i + 3];
        float2 v0 = hs[(size_t)r0 * 32 + lane];
        float2 v1 = hs[(size_t)r1 * 32 + lane];
        float2 v2 = hs[(size_t)r2 * 32 + lane];
        float2 v3 = hs[(size_t)r3 * 32 + lane];
        acc.x += (v0.x + v1.x) + (v2.x + v3.x);
        acc.y += (v0.y + v1.y) + (v2.y + v3.y);
    }
    for (; i < e; i++) {
        float2 v = hs[(size_t)g_adj[i] * 32 + lane];
        acc.x += v.x; acc.y += v.y;
    }

    float d = g_dinv[c];
    float2 bb = ((const float2*)b)[lane];
    acc.x = acc.x * d + bb.x;
    acc.y = acc.y * d + bb.y;
    ((float2*)out)[(size_t)c * 32 + lane] = acc;
}

// ---------------- launch ----------------
extern "C" void kernel_launch(void* const* d_in, const int* in_sizes, int n_in,
                              void* d_out, int out_size)
{
    const float* x      = (const float*)d_in[0];
    const int*   ei_raw = (const int*)d_in[1];
    const float* W1 = (const float*)d_in[2];
    const float* b1 = (const float*)d_in[3];
    const float* W2 = (const float*)d_in[4];
    const float* b2 = (const float*)d_in[5];
    const float* W3 = (const float*)d_in[6];
    const float* b3 = (const float*)d_in[7];
    float* out = (float*)d_out;

    // ---- CSR build + normalization ----
    detect_kernel<<<1, 256>>>(ei_raw);
    zero_deg_kernel<<<NB, 256>>>();
    decode_count_kernel<<<(N_EDGES + 255) / 256, 256>>>(ei_raw);
    scanA_kernel<<<NB, 256>>>();
    scanB_kernel<<<1, 256>>>();
    scanC_kernel<<<NB, 256>>>();
    fill_kernel<<<(N_EDGES + 255) / 256, 256>>>();

    const int gridRows = (N_NODES + BM - 1) / BM;          // 782
    const int aggGrid  = (N_NODES * 32 + 255) / 256;       // warp per node

    // ---- layer 1 ----
    gemm_xh_kernel<<<dim3(128 / BN, gridRows), 256>>>(x, W1, 128, 128);
    agg128_kernel<true><<<aggGrid, 256>>>(b1);

    // ---- layer 2 ----
    gemm_oh_kernel<<<dim3(128 / BN, gridRows), 256>>>(W2, 128, 128);
    agg128_kernel<true><<<aggGrid, 256>>>(b2);

    // ---- layer 3 (dim 64 -> d_out) ----
    gemm_oh_kernel<<<dim3(64 / BN, gridRows), 256>>>(W3, 64, 128);
    agg64_kernel<<<aggGrid, 256>>>(out, b3);
}

// round 7
// speedup vs baseline: 2.7933x; 1.8279x over previous
#include <cuda_runtime.h>
#include <stdint.h>

#define N_NODES 50000
#define N_EDGES 800000
#define NB      208            // scan blocks: 208*256 = 53248 >= N_NODES

// ---------------- scratch (allocation-free: __device__ globals) ----------------
__device__ __align__(16) float g_dinv[N_NODES];
__device__ __align__(16) float g_h[N_NODES * 128];   // GEMM output, pre-scaled by dinv[row]
__device__ __align__(16) float g_o[N_NODES * 128];   // layer output
__device__ int g_row[N_EDGES];
__device__ int g_col[N_EDGES];
__device__ int g_adj[N_EDGES];        // CSR: source nodes grouped by dest
__device__ int g_off[N_NODES + 1];    // CSR offsets
__device__ int g_cur[N_NODES];        // fill cursors
__device__ int g_degi[N_NODES];       // in-degree (edges only)
__device__ int g_bsum[NB];            // per-block degree sums
__device__ int g_bpref[NB];           // exclusive prefix of block sums
__device__ int g_is64;

// ---------------- edge-index dtype detection ----------------
__global__ void detect_kernel(const int* __restrict__ ei_raw) {
    __shared__ int any;
    if (threadIdx.x == 0) any = 0;
    __syncthreads();
    int nz = 0;
    for (int i = threadIdx.x; i < 1024; i += blockDim.x)
        nz |= ei_raw[2 * i + 1];
    if (nz) atomicOr(&any, 1);
    __syncthreads();
    if (threadIdx.x == 0) g_is64 = (any == 0);
}

__global__ void zero_deg_kernel() {
    int i = blockIdx.x * blockDim.x + threadIdx.x;
    if (i < N_NODES) g_degi[i] = 0;
}

// decode + degree count fused (one 800K pass)
__global__ void decode_count_kernel(const int* __restrict__ ei_raw) {
    int i = blockIdx.x * blockDim.x + threadIdx.x;
    if (i >= N_EDGES) return;
    int r, c;
    if (g_is64) {
        r = ei_raw[2 * i];
        c = ei_raw[2 * (N_EDGES + i)];
    } else {
        r = ei_raw[i];
        c = ei_raw[N_EDGES + i];
    }
    g_row[i] = r;
    g_col[i] = c;
    atomicAdd(&g_degi[c], 1);
}

// ---------------- 3-phase parallel exclusive scan over degrees ----------------
__global__ __launch_bounds__(256) void scanA_kernel() {
    __shared__ int sh[256];
    int i = blockIdx.x * 256 + threadIdx.x;
    int v = (i < N_NODES) ? g_degi[i] : 0;
    sh[threadIdx.x] = v;
    __syncthreads();
    for (int o = 128; o > 0; o >>= 1) {
        if (threadIdx.x < o) sh[threadIdx.x] += sh[threadIdx.x + o];
        __syncthreads();
    }
    if (threadIdx.x == 0) g_bsum[blockIdx.x] = sh[0];
}

__global__ __launch_bounds__(256) void scanB_kernel() {
    __shared__ int sh[256];
    int t = threadIdx.x;
    int v = (t < NB) ? g_bsum[t] : 0;
    sh[t] = v;
    __syncthreads();
    for (int o = 1; o < 256; o <<= 1) {
        int x = sh[t];
        int a = (t >= o) ? sh[t - o] : 0;
        __syncthreads();
        sh[t] = x + a;
        __syncthreads();
    }
    if (t < NB) g_bpref[t] = sh[t] - v;   // exclusive
    if (t == 255) g_off[N_NODES] = sh[255];
}

__global__ __launch_bounds__(256) void scanC_kernel() {
    __shared__ int sh[256];
    int t = threadIdx.x;
    int i = blockIdx.x * 256 + t;
    int d = (i < N_NODES) ? g_degi[i] : 0;
    sh[t] = d;
    __syncthreads();
    for (int o = 1; o < 256; o <<= 1) {
        int x = sh[t];
        int a = (t >= o) ? sh[t - o] : 0;
        __syncthreads();
        sh[t] = x + a;
        __syncthreads();
    }
    if (i < N_NODES) {
        int excl = sh[t] - d + g_bpref[blockIdx.x];
        g_off[i] = excl;
        g_cur[i] = excl;
        g_dinv[i] = rsqrtf((float)(1 + d));   // +1 self-loop
    }
}

__global__ void fill_kernel() {
    int i = blockIdx.x * blockDim.x + threadIdx.x;
    if (i >= N_EDGES) return;
    int c = g_col[i];
    int pos = atomicAdd(&g_cur[c], 1);
    g_adj[pos] = g_row[i];
}

// ---------------- tf32 tensor-core GEMM: g_h[m,:] = dinv[m]*(A @ B)[m,:] ----------------
// Block tile 128 x BN, 8 warps (2M x 4N), warp tile 64 x (BN/4).
// mma.sync.aligned.m16n8k8.row.col.f32.tf32.tf32.f32

__device__ __forceinline__ unsigned f2tf32(float f) {
    unsigned r;
    asm("cvt.rna.tf32.f32 %0, %1;" : "=r"(r) : "f"(f));
    return r;
}

template <int BN, int SRC>   // SRC=0: A = Aext, SRC=1: A = g_o
__global__ __launch_bounds__(256) void gemm_tc_kernel(
    const float* __restrict__ Aext, const float* __restrict__ B)
{
    constexpr int WN = BN / 4;     // warp N tile (32 or 16)
    constexpr int NF = WN / 8;     // n fragments per warp (4 or 2)
    constexpr int BK = 32;

    __shared__ unsigned As[128][BK + 4];   // [m][k], tf32 bits
    __shared__ unsigned Bs[BK][BN + 8];    // [k][n], +8 pad: conflict-free frag loads

    const float* A = (SRC == 0) ? Aext : g_o;
    int tid  = threadIdx.x;
    int warp = tid >> 5;
    int lane = tid & 31;
    int gid  = lane >> 2;          // 0..7
    int tig  = lane & 3;           // 0..3
    int warp_m = warp >> 2;        // 0..1
    int warp_n = warp & 3;         // 0..3
    int rowBase = blockIdx.y * 128;

    float acc[4][NF][4];
#pragma unroll
    for (int mf = 0; mf < 4; mf++)
#pragma unroll
        for (int nf = 0; nf < NF; nf++)
#pragma unroll
            for (int q = 0; q < 4; q++) acc[mf][nf][q] = 0.0f;

    for (int kc = 0; kc < 128; kc += BK) {
        // stage A tile 128x32 (16 elems/thread), convert to tf32
#pragma unroll
        for (int i = 0; i < 16; i++) {
            int idx = tid + i * 256;
            int m = idx >> 5;
            int k = idx & 31;
            int gm = rowBase + m;
            float v = (gm < N_NODES) ? A[(size_t)gm * 128 + kc + k] : 0.0f;
            As[m][k] = f2tf32(v);
        }
        // stage B tile 32xBN
#pragma unroll
        for (int i = 0; i < (32 * BN) / 256; i++) {
            int idx = tid + i * 256;
            int k = idx / BN;
            int n = idx % BN;
            Bs[k][n] = f2tf32(B[(size_t)(kc + k) * BN + n]);
        }
        __syncthreads();

#pragma unroll
        for (int ks = 0; ks < BK / 8; ks++) {
            int k0 = ks * 8;
            unsigned a[4][4];
#pragma unroll
            for (int mf = 0; mf < 4; mf++) {
                int rb = warp_m * 64 + mf * 16;
                a[mf][0] = As[rb + gid][k0 + tig];
                a[mf][1] = As[rb + gid + 8][k0 + tig];
                a[mf][2] = As[rb + gid][k0 + tig + 4];
                a[mf][3] = As[rb + gid + 8][k0 + tig + 4];
            }
#pragma unroll
            for (int nf = 0; nf < NF; nf++) {
                int nb = warp_n * WN + nf * 8;
                unsigned b0 = Bs[k0 + tig][nb + gid];
                unsigned b1 = Bs[k0 + tig + 4][nb + gid];
#pragma unroll
                for (int mf = 0; mf < 4; mf++) {
                    asm volatile(
                        "mma.sync.aligned.m16n8k8.row.col.f32.tf32.tf32.f32 "
                        "{%0,%1,%2,%3}, {%4,%5,%6,%7}, {%8,%9}, {%0,%1,%2,%3};"
                        : "+f"(acc[mf][nf][0]), "+f"(acc[mf][nf][1]),
                          "+f"(acc[mf][nf][2]), "+f"(acc[mf][nf][3])
                        : "r"(a[mf][0]), "r"(a[mf][1]),
                          "r"(a[mf][2]), "r"(a[mf][3]),
                          "r"(b0), "r"(b1));
                }
            }
        }
        __syncthreads();
    }

    // epilogue: scale rows by dinv, store to g_h
#pragma unroll
    for (int mf = 0; mf < 4; mf++) {
        int r0 = rowBase + warp_m * 64 + mf * 16 + gid;
        int r1 = r0 + 8;
        float d0 = (r0 < N_NODES) ? g_dinv[r0] : 0.0f;
        float d1 = (r1 < N_NODES) ? g_dinv[r1] : 0.0f;
#pragma unroll
        for (int nf = 0; nf < NF; nf++) {
            int nc = warp_n * WN + nf * 8 + tig * 2;
            if (r0 < N_NODES) {
                float2 v = make_float2(acc[mf][nf][0] * d0, acc[mf][nf][1] * d0);
                *(float2*)&g_h[(size_t)r0 * BN + nc] = v;
            }
            if (r1 < N_NODES) {
                float2 v = make_float2(acc[mf][nf][2] * d1, acc[mf][nf][3] * d1);
                *(float2*)&g_h[(size_t)r1 * BN + nc] = v;
            }
        }
    }
}

// ---------------- CSR aggregate (warp per node), DIM=128, float4 lanes ----------------
// out[c] = relu?( dinv[c] * (hs[c] + sum_{r in adj[c]} hs[r]) + b )
template <bool RELU>
__global__ __launch_bounds__(256) void agg128_kernel(const float* __restrict__ b)
{
    int warp = (blockIdx.x * blockDim.x + threadIdx.x) >> 5;
    int lane = threadIdx.x & 31;
    if (warp >= N_NODES) return;
    int c = warp;

    const float4* hs = (const float4*)g_h;
    float4 acc = hs[(size_t)c * 32 + lane];          // self-loop term

    int s = g_off[c], e = g_off[c + 1];
    int i = s;
    for (; i + 4 <= e; i += 4) {
        int r0 = g_adj[i], r1 = g_adj[i + 1], r2 = g_adj[i + 2], r3 = g_adj[i + 3];
        float4 v0 = hs[(size_t)r0 * 32 + lane];
        float4 v1 = hs[(size_t)r1 * 32 + lane];
        float4 v2 = hs[(size_t)r2 * 32 + lane];
        float4 v3 = hs[(size_t)r3 * 32 + lane];
        acc.x += (v0.x + v1.x) + (v2.x + v3.x);
        acc.y += (v0.y + v1.y) + (v2.y + v3.y);
        acc.z += (v0.z + v1.z) + (v2.z + v3.z);
        acc.w += (v0.w + v1.w) + (v2.w + v3.w);
    }
    for (; i < e; i++) {
        float4 v = hs[(size_t)g_adj[i] * 32 + lane];
        acc.x += v.x; acc.y += v.y; acc.z += v.z; acc.w += v.w;
    }

    float d = g_dinv[c];
    float4 bb = ((const float4*)b)[lane];
    acc.x = acc.x * d + bb.x;
    acc.y = acc.y * d + bb.y;
    acc.z = acc.z * d + bb.z;
    acc.w = acc.w * d + bb.w;
    if (RELU) {
        acc.x = fmaxf(acc.x, 0.0f); acc.y = fmaxf(acc.y, 0.0f);
        acc.z = fmaxf(acc.z, 0.0f); acc.w = fmaxf(acc.w, 0.0f);
    }
    ((float4*)g_o)[(size_t)c * 32 + lane] = acc;
}

// DIM=64 final layer: float2 lanes, writes d_out, no relu
__global__ __launch_bounds__(256) void agg64_kernel(float* __restrict__ out,
                                                    const float* __restrict__ b)
{
    int warp = (blockIdx.x * blockDim.x + threadIdx.x) >> 5;
    int lane = threadIdx.x & 31;
    if (warp >= N_NODES) return;
    int c = warp;

    const float2* hs = (const float2*)g_h;
    float2 acc = hs[(size_t)c * 32 + lane];

    int s = g_off[c], e = g_off[c + 1];
    int i = s;
    for (; i + 4 <= e; i += 4) {
        int r0 = g_adj[i], r1 = g_adj[i + 1], r2 = g_adj[i + 2], r3 = g_adj[i + 3];
        float2 v0 = hs[(size_t)r0 * 32 + lane];
        float2 v1 = hs[(size_t)r1 * 32 + lane];
        float2 v2 = hs[(size_t)r2 * 32 + lane];
        float2 v3 = hs[(size_t)r3 * 32 + lane];
        acc.x += (v0.x + v1.x) + (v2.x + v3.x);
        acc.y += (v0.y + v1.y) + (v2.y + v3.y);
    }
    for (; i < e; i++) {
        float2 v = hs[(size_t)g_adj[i] * 32 + lane];
        acc.x += v.x; acc.y += v.y;
    }

    float d = g_dinv[c];
    float2 bb = ((const float2*)b)[lane];
    acc.x = acc.x * d + bb.x;
    acc.y = acc.y * d + bb.y;
    ((float2*)out)[(size_t)c * 32 + lane] = acc;
}

// ---------------- launch ----------------
extern "C" void kernel_launch(void* const* d_in, const int* in_sizes, int n_in,
                              void* d_out, int out_size)
{
    const float* x      = (const float*)d_in[0];
    const int*   ei_raw = (const int*)d_in[1];
    const float* W1 = (const float*)d_in[2];
    const float* b1 = (const float*)d_in[3];
    const float* W2 = (const float*)d_in[4];
    const float* b2 = (const float*)d_in[5];
    const float* W3 = (const float*)d_in[6];
    const float* b3 = (const float*)d_in[7];
    float* out = (float*)d_out;

    // ---- CSR build + normalization ----
    detect_kernel<<<1, 256>>>(ei_raw);
    zero_deg_kernel<<<NB, 256>>>();
    decode_count_kernel<<<(N_EDGES + 255) / 256, 256>>>(ei_raw);
    scanA_kernel<<<NB, 256>>>();
    scanB_kernel<<<1, 256>>>();
    scanC_kernel<<<NB, 256>>>();
    fill_kernel<<<(N_EDGES + 255) / 256, 256>>>();

    const int gemmRows = (N_NODES + 127) / 128;            // 391
    const int aggGrid  = (N_NODES * 32 + 255) / 256;       // warp per node

    // ---- layer 1 ----
    gemm_tc_kernel<128, 0><<<dim3(1, gemmRows), 256>>>(x, W1);
    agg128_kernel<true><<<aggGrid, 256>>>(b1);

    // ---- layer 2 ----
    gemm_tc_kernel<128, 1><<<dim3(1, gemmRows), 256>>>(nullptr, W2);
    agg128_kernel<true><<<aggGrid, 256>>>(b2);

    // ---- layer 3 (dim 64 -> d_out) ----
    gemm_tc_kernel<64, 1><<<dim3(1, gemmRows), 256>>>(nullptr, W3);
    agg64_kernel<<<aggGrid, 256>>>(out, b3);
}

// round 9
// speedup vs baseline: 2.9229x; 1.0464x over previous
#include <cuda_runtime.h>
#include <cuda_fp16.h>
#include <stdint.h>

#define N_NODES 50000
#define N_EDGES 800000
#define NB      208            // scan blocks: 208*256 = 53248 >= N_NODES

// ---------------- scratch (allocation-free: __device__ globals) ----------------
__device__ __align__(16) float  g_dinv[N_NODES];
__device__ __align__(16) __half g_h16[N_NODES * 128]; // GEMM out, dinv-prescaled, fp16
__device__ __align__(16) float  g_o[N_NODES * 128];   // layer output (fp32, next GEMM input)
__device__ int g_row[N_EDGES];
__device__ int g_col[N_EDGES];
__device__ int g_adj[N_EDGES];        // CSR: source nodes grouped by dest
__device__ int g_off[N_NODES + 1];    // CSR offsets
__device__ int g_cur[N_NODES];        // fill cursors
__device__ int g_degi[N_NODES];       // in-degree (edges only)
__device__ int g_bsum[NB];            // per-block degree sums
__device__ int g_bpref[NB];           // exclusive prefix of block sums
__device__ int g_is64;

// ---------------- edge-index dtype detection ----------------
__global__ void detect_kernel(const int* __restrict__ ei_raw) {
    __shared__ int any;
    if (threadIdx.x == 0) any = 0;
    __syncthreads();
    int nz = 0;
    for (int i = threadIdx.x; i < 1024; i += blockDim.x)
        nz |= ei_raw[2 * i + 1];
    if (nz) atomicOr(&any, 1);
    __syncthreads();
    if (threadIdx.x == 0) g_is64 = (any == 0);
}

__global__ void zero_deg_kernel() {
    int i = blockIdx.x * blockDim.x + threadIdx.x;
    if (i < N_NODES) g_degi[i] = 0;
}

// decode + degree count fused (one 800K pass)
__global__ void decode_count_kernel(const int* __restrict__ ei_raw) {
    int i = blockIdx.x * blockDim.x + threadIdx.x;
    if (i >= N_EDGES) return;
    int r, c;
    if (g_is64) {
        r = ei_raw[2 * i];
        c = ei_raw[2 * (N_EDGES + i)];
    } else {
        r = ei_raw[i];
        c = ei_raw[N_EDGES + i];
    }
    g_row[i] = r;
    g_col[i] = c;
    atomicAdd(&g_degi[c], 1);
}

// ---------------- 3-phase parallel exclusive scan over degrees ----------------
__global__ __launch_bounds__(256) void scanA_kernel() {
    __shared__ int sh[256];
    int i = blockIdx.x * 256 + threadIdx.x;
    int v = (i < N_NODES) ? g_degi[i] : 0;
    sh[threadIdx.x] = v;
    __syncthreads();
    for (int o = 128; o > 0; o >>= 1) {
        if (threadIdx.x < o) sh[threadIdx.x] += sh[threadIdx.x + o];
        __syncthreads();
    }
    if (threadIdx.x == 0) g_bsum[blockIdx.x] = sh[0];
}

__global__ __launch_bounds__(256) void scanB_kernel() {
    __shared__ int sh[256];
    int t = threadIdx.x;
    int v = (t < NB) ? g_bsum[t] : 0;
    sh[t] = v;
    __syncthreads();
    for (int o = 1; o < 256; o <<= 1) {
        int x = sh[t];
        int a = (t >= o) ? sh[t - o] : 0;
        __syncthreads();
        sh[t] = x + a;
        __syncthreads();
    }
    if (t < NB) g_bpref[t] = sh[t] - v;   // exclusive
    if (t == 255) g_off[N_NODES] = sh[255];
}

__global__ __launch_bounds__(256) void scanC_kernel() {
    __shared__ int sh[256];
    int t = threadIdx.x;
    int i = blockIdx.x * 256 + t;
    int d = (i < N_NODES) ? g_degi[i] : 0;
    sh[t] = d;
    __syncthreads();
    for (int o = 1; o < 256; o <<= 1) {
        int x = sh[t];
        int a = (t >= o) ? sh[t - o] : 0;
        __syncthreads();
        sh[t] = x + a;
        __syncthreads();
    }
    if (i < N_NODES) {
        int excl = sh[t] - d + g_bpref[blockIdx.x];
        g_off[i] = excl;
        g_cur[i] = excl;
        g_dinv[i] = rsqrtf((float)(1 + d));   // +1 self-loop
    }
}

__global__ void fill_kernel() {
    int i = blockIdx.x * blockDim.x + threadIdx.x;
    if (i >= N_EDGES) return;
    int c = g_col[i];
    int pos = atomicAdd(&g_cur[c], 1);
    g_adj[pos] = g_row[i];
}

// ---------------- tf32 tensor-core GEMM: g_h16[m,:] = fp16( dinv[m]*(A @ B)[m,:] ) ----------------
// Block tile 128 x BN, 8 warps (2M x 4N), warp tile 64 x (BN/4).

__device__ __forceinline__ unsigned f2tf32(float f) {
    unsigned r;
    asm("cvt.rna.tf32.f32 %0, %1;" : "=r"(r) : "f"(f));
    return r;
}

template <int BN, int SRC>   // SRC=0: A = Aext, SRC=1: A = g_o
__global__ __launch_bounds__(256) void gemm_tc_kernel(
    const float* __restrict__ Aext, const float* __restrict__ B)
{
    constexpr int WN = BN / 4;     // warp N tile (32 or 16)
    constexpr int NF = WN / 8;     // n fragments per warp (4 or 2)
    constexpr int BK = 32;

    __shared__ unsigned As[128][BK + 4];   // [m][k], tf32 bits
    __shared__ unsigned Bs[BK][BN + 8];    // [k][n], +8 pad: conflict-free frag loads

    const float* A = (SRC == 0) ? Aext : g_o;
    int tid  = threadIdx.x;
    int warp = tid >> 5;
    int lane = tid & 31;
    int gid  = lane >> 2;          // 0..7
    int tig  = lane & 3;           // 0..3
    int warp_m = warp >> 2;        // 0..1
    int warp_n = warp & 3;         // 0..3
    int rowBase = blockIdx.y * 128;

    float acc[4][NF][4];
#pragma unroll
    for (int mf = 0; mf < 4; mf++)
#pragma unroll
        for (int nf = 0; nf < NF; nf++)
#pragma unroll
            for (int q = 0; q < 4; q++) acc[mf][nf][q] = 0.0f;

    for (int kc = 0; kc < 128; kc += BK) {
        // stage A tile 128x32 (16 elems/thread), convert to tf32
#pragma unroll
        for (int i = 0; i < 16; i++) {
            int idx = tid + i * 256;
            int m = idx >> 5;
            int k = idx & 31;
            int gm = rowBase + m;
            float v = (gm < N_NODES) ? A[(size_t)gm * 128 + kc + k] : 0.0f;
            As[m][k] = f2tf32(v);
        }
        // stage B tile 32xBN
#pragma unroll
        for (int i = 0; i < (32 * BN) / 256; i++) {
            int idx = tid + i * 256;
            int k = idx / BN;
            int n = idx % BN;
            Bs[k][n] = f2tf32(B[(size_t)(kc + k) * BN + n]);
        }
        __syncthreads();

#pragma unroll
        for (int ks = 0; ks < BK / 8; ks++) {
            int k0 = ks * 8;
            unsigned a[4][4];
#pragma unroll
            for (int mf = 0; mf < 4; mf++) {
                int rb = warp_m * 64 + mf * 16;
                a[mf][0] = As[rb + gid][k0 + tig];
                a[mf][1] = As[rb + gid + 8][k0 + tig];
                a[mf][2] = As[rb + gid][k0 + tig + 4];
                a[mf][3] = As[rb + gid + 8][k0 + tig + 4];
            }
#pragma unroll
            for (int nf = 0; nf < NF; nf++) {
                int nb = warp_n * WN + nf * 8;
                unsigned b0 = Bs[k0 + tig][nb + gid];
                unsigned b1 = Bs[k0 + tig + 4][nb + gid];
#pragma unroll
                for (int mf = 0; mf < 4; mf++) {
                    asm volatile(
                        "mma.sync.aligned.m16n8k8.row.col.f32.tf32.tf32.f32 "
                        "{%0,%1,%2,%3}, {%4,%5,%6,%7}, {%8,%9}, {%0,%1,%2,%3};"
                        : "+f"(acc[mf][nf][0]), "+f"(acc[mf][nf][1]),
                          "+f"(acc[mf][nf][2]), "+f"(acc[mf][nf][3])
                        : "r"(a[mf][0]), "r"(a[mf][1]),
                          "r"(a[mf][2]), "r"(a[mf][3]),
                          "r"(b0), "r"(b1));
                }
            }
        }
        __syncthreads();
    }

    // epilogue: scale rows by dinv, pack to half2, store to g_h16
#pragma unroll
    for (int mf = 0; mf < 4; mf++) {
        int r0 = rowBase + warp_m * 64 + mf * 16 + gid;
        int r1 = r0 + 8;
        float d0 = (r0 < N_NODES) ? g_dinv[r0] : 0.0f;
        float d1 = (r1 < N_NODES) ? g_dinv[r1] : 0.0f;
#pragma unroll
        for (int nf = 0; nf < NF; nf++) {
            int nc = warp_n * WN + nf * 8 + tig * 2;
            if (r0 < N_NODES) {
                __half2 hv = __floats2half2_rn(acc[mf][nf][0] * d0, acc[mf][nf][1] * d0);
                *(__half2*)&g_h16[(size_t)r0 * BN + nc] = hv;
            }
            if (r1 < N_NODES) {
                __half2 hv = __floats2half2_rn(acc[mf][nf][2] * d1, acc[mf][nf][3] * d1);
                *(__half2*)&g_h16[(size_t)r1 * BN + nc] = hv;
            }
        }
    }
}

// ---------------- CSR aggregate (warp per node), DIM=128, fp16 gather ----------------
// o[c] = relu?( dinv[c] * (hs[c] + sum_{r in adj[c]} hs[r]) + b ), hs fp16, accum fp32.
// Row = 128 halfs = 256B = 32 uint2; lane j holds features 4j..4j+3 (one uint2).
template <bool RELU>
__global__ __launch_bounds__(256) void agg128_kernel(const float* __restrict__ b)
{
    int warp = (blockIdx.x * blockDim.x + threadIdx.x) >> 5;
    int lane = threadIdx.x & 31;
    if (warp >= N_NODES) return;
    int c = warp;

    const uint2* hs = (const uint2*)g_h16;   // 32 uint2 per row

    uint2 u = hs[(size_t)c * 32 + lane];
    float2 f0 = __half22float2(*(const __half2*)&u.x);
    float2 f1 = __half22float2(*(const __half2*)&u.y);
    float a0 = f0.x, a1 = f0.y, a2 = f1.x, a3 = f1.y;   // self-loop term

    int s = g_off[c], e = g_off[c + 1];
    int i = s;
    for (; i + 4 <= e; i += 4) {
        int r0 = g_adj[i], r1 = g_adj[i + 1], r2 = g_adj[i + 2], r3 = g_adj[i + 3];
        uint2 u0 = hs[(size_t)r0 * 32 + lane];
        uint2 u1 = hs[(size_t)r1 * 32 + lane];
        uint2 u2 = hs[(size_t)r2 * 32 + lane];
        uint2 u3 = hs[(size_t)r3 * 32 + lane];
        float2 p;
        p = __half22float2(*(const __half2*)&u0.x); a0 += p.x; a1 += p.y;
        p = __half22float2(*(const __half2*)&u0.y); a2 += p.x; a3 += p.y;
        p = __half22float2(*(const __half2*)&u1.x); a0 += p.x; a1 += p.y;
        p = __half22float2(*(const __half2*)&u1.y); a2 += p.x; a3 += p.y;
        p = __half22float2(*(const __half2*)&u2.x); a0 += p.x; a1 += p.y;
        p = __half22float2(*(const __half2*)&u2.y); a2 += p.x; a3 += p.y;
        p = __half22float2(*(const __half2*)&u3.x); a0 += p.x; a1 += p.y;
        p = __half22float2(*(const __half2*)&u3.y); a2 += p.x; a3 += p.y;
    }
    for (; i < e; i++) {
        uint2 uv = hs[(size_t)g_adj[i] * 32 + lane];
        float2 p;
        p = __half22float2(*(const __half2*)&uv.x); a0 += p.x; a1 += p.y;
        p = __half22float2(*(const __half2*)&uv.y); a2 += p.x; a3 += p.y;
    }

    float d = g_dinv[c];
    float4 bb = ((const float4*)b)[lane];
    float4 r;
    r.x = a0 * d + bb.x;
    r.y = a1 * d + bb.y;
    r.z = a2 * d + bb.z;
    r.w = a3 * d + bb.w;
    if (RELU) {
        r.x = fmaxf(r.x, 0.0f); r.y = fmaxf(r.y, 0.0f);
        r.z = fmaxf(r.z, 0.0f); r.w = fmaxf(r.w, 0.0f);
    }
    ((float4*)g_o)[(size_t)c * 32 + lane] = r;
}

// DIM=64 final layer: lane handles 2 features (one half2 = 4B per row), writes d_out fp32.
__global__ __launch_bounds__(256) void agg64_kernel(float* __restrict__ out,
                                                    const float* __restrict__ b)
{
    int warp = (blockIdx.x * blockDim.x + threadIdx.x) >> 5;
    int lane = threadIdx.x & 31;
    if (warp >= N_NODES) return;
    int c = warp;

    const unsigned* hs = (const unsigned*)g_h16;   // 32 half2 per 64-dim row

    unsigned u = hs[(size_t)c * 32 + lane];
    float2 f = __half22float2(*(const __half2*)&u);
    float a0 = f.x, a1 = f.y;

    int s = g_off[c], e = g_off[c + 1];
    int i = s;
    for (; i + 4 <= e; i += 4) {
        int r0 = g_adj[i], r1 = g_adj[i + 1], r2 = g_adj[i + 2], r3 = g_adj[i + 3];
        unsigned u0 = hs[(size_t)r0 * 32 + lane];
        unsigned u1 = hs[(size_t)r1 * 32 + lane];
        unsigned u2 = hs[(size_t)r2 * 32 + lane];
        unsigned u3 = hs[(size_t)r3 * 32 + lane];
        float2 p;
        p = __half22float2(*(const __half2*)&u0); a0 += p.x; a1 += p.y;
        p = __half22float2(*(const __half2*)&u1); a0 += p.x; a1 += p.y;
        p = __half22float2(*(const __half2*)&u2); a0 += p.x; a1 += p.y;
        p = __half22float2(*(const __half2*)&u3); a0 += p.x; a1 += p.y;
    }
    for (; i < e; i++) {
        unsigned uv = hs[(size_t)g_adj[i] * 32 + lane];
        float2 p = __half22float2(*(const __half2*)&uv);
        a0 += p.x; a1 += p.y;
    }

    float d = g_dinv[c];
    float2 bb = ((const float2*)b)[lane];
    float2 r;
    r.x = a0 * d + bb.x;
    r.y = a1 * d + bb.y;
    ((float2*)out)[(size_t)c * 32 + lane] = r;
}

// ---------------- launch ----------------
extern "C" void kernel_launch(void* const* d_in, const int* in_sizes, int n_in,
                              void* d_out, int out_size)
{
    const float* x      = (const float*)d_in[0];
    const int*   ei_raw = (const int*)d_in[1];
    const float* W1 = (const float*)d_in[2];
    const float* b1 = (const float*)d_in[3];
    const float* W2 = (const float*)d_in[4];
    const float* b2 = (const float*)d_in[5];
    const float* W3 = (const float*)d_in[6];
    const float* b3 = (const float*)d_in[7];
    float* out = (float*)d_out;

    // ---- CSR build + normalization ----
    detect_kernel<<<1, 256>>>(ei_raw);
    zero_deg_kernel<<<NB, 256>>>();
    decode_count_kernel<<<(N_EDGES + 255) / 256, 256>>>(ei_raw);
    scanA_kernel<<<NB, 256>>>();
    scanB_kernel<<<1, 256>>>();
    scanC_kernel<<<NB, 256>>>();
    fill_kernel<<<(N_EDGES + 255) / 256, 256>>>();

    const int gemmRows = (N_NODES + 127) / 128;            // 391
    const int aggGrid  = (N_NODES * 32 + 255) / 256;       // warp per node

    // ---- layer 1 ----
    gemm_tc_kernel<128, 0><<<dim3(1, gemmRows), 256>>>(x, W1);
    agg128_kernel<true><<<aggGrid, 256>>>(b1);

    // ---- layer 2 ----
    gemm_tc_kernel<128, 1><<<dim3(1, gemmRows), 256>>>(nullptr, W2);
    agg128_kernel<true><<<aggGrid, 256>>>(b2);

    // ---- layer 3 (dim 64 -> d_out) ----
    gemm_tc_kernel<64, 1><<<dim3(1, gemmRows), 256>>>(nullptr, W3);
    agg64_kernel<<<aggGrid, 256>>>(out, b3);
}

// round 10
// speedup vs baseline: 3.1548x; 1.0793x over previous
#include <cuda_runtime.h>
#include <cuda_fp16.h>
#include <stdint.h>

#define N_NODES 50000
#define N_EDGES 800000
#define NB      208            // scan blocks: 208*256 = 53248 >= N_NODES

// ---------------- scratch (allocation-free: __device__ globals) ----------------
__device__ __align__(16) float  g_dinv[N_NODES];
__device__ __align__(16) __half g_h16[N_NODES * 128]; // GEMM out, dinv-prescaled, fp16
__device__ __align__(16) float  g_o[N_NODES * 128];   // layer output (fp32, next GEMM input)
__device__ int g_adj[N_EDGES];        // CSR: source nodes grouped by dest
__device__ int g_off[N_NODES + 1];    // CSR offsets
__device__ int g_cur[N_NODES];        // fill cursors
__device__ int g_degi[N_NODES];       // in-degree (edges only)
__device__ int g_bsum[NB];            // per-block degree sums
__device__ int g_is64;

// ---------------- detect dtype + zero degrees (one launch) ----------------
__global__ void detect_zero_kernel(const int* __restrict__ ei_raw) {
    int i = blockIdx.x * 256 + threadIdx.x;
    if (i < N_NODES) g_degi[i] = 0;
    if (blockIdx.x == 0) {
        __shared__ int any;
        if (threadIdx.x == 0) any = 0;
        __syncthreads();
        int nz = 0;
        for (int j = threadIdx.x; j < 1024; j += 256)
            nz |= ei_raw[2 * j + 1];
        if (nz) atomicOr(&any, 1);
        __syncthreads();
        if (threadIdx.x == 0) g_is64 = (any == 0);
    }
}

// degree count straight from raw edge buffer
__global__ void count_kernel(const int* __restrict__ ei_raw) {
    int i = blockIdx.x * blockDim.x + threadIdx.x;
    if (i >= N_EDGES) return;
    int c = g_is64 ? ei_raw[2 * (N_EDGES + i)] : ei_raw[N_EDGES + i];
    atomicAdd(&g_degi[c], 1);
}

// ---------------- scan phase A: per-block degree sums ----------------
__global__ __launch_bounds__(256) void scanA_kernel() {
    __shared__ int sh[256];
    int i = blockIdx.x * 256 + threadIdx.x;
    int v = (i < N_NODES) ? g_degi[i] : 0;
    sh[threadIdx.x] = v;
    __syncthreads();
    for (int o = 128; o > 0; o >>= 1) {
        if (threadIdx.x < o) sh[threadIdx.x] += sh[threadIdx.x + o];
        __syncthreads();
    }
    if (threadIdx.x == 0) g_bsum[blockIdx.x] = sh[0];
}

// ---------------- scan phase B+C merged: offsets, cursors, dinv ----------------
__global__ __launch_bounds__(256) void scanBC_kernel() {
    __shared__ int pre[256];
    __shared__ int sh[256];
    int t = threadIdx.x;

    // block prefix = sum of bsum[j], j < blockIdx.x
    pre[t] = (t < NB && t < blockIdx.x) ? g_bsum[t] : 0;
    __syncthreads();
    for (int o = 128; o > 0; o >>= 1) {
        if (t < o) pre[t] += pre[t + o];
        __syncthreads();
    }
    int bpref = pre[0];

    // intra-block inclusive scan of degrees
    int i = blockIdx.x * 256 + t;
    int d = (i < N_NODES) ? g_degi[i] : 0;
    sh[t] = d;
    __syncthreads();
    for (int o = 1; o < 256; o <<= 1) {
        int x = sh[t];
        int a = (t >= o) ? sh[t - o] : 0;
        __syncthreads();
        sh[t] = x + a;
        __syncthreads();
    }
    if (i < N_NODES) {
        int excl = sh[t] - d + bpref;
        g_off[i] = excl;
        g_cur[i] = excl;
        g_dinv[i] = rsqrtf((float)(1 + d));   // +1 self-loop
    }
    if (i == 0) g_off[N_NODES] = N_EDGES;
}

// fill CSR straight from raw edge buffer
__global__ void fill_kernel(const int* __restrict__ ei_raw) {
    int i = blockIdx.x * blockDim.x + threadIdx.x;
    if (i >= N_EDGES) return;
    int r, c;
    if (g_is64) {
        r = ei_raw[2 * i];
        c = ei_raw[2 * (N_EDGES + i)];
    } else {
        r = ei_raw[i];
        c = ei_raw[N_EDGES + i];
    }
    int pos = atomicAdd(&g_cur[c], 1);
    g_adj[pos] = r;
}

// ---------------- tf32 tensor-core GEMM: g_h16[m,:] = fp16( dinv[m]*(A @ B)[m,:] ) ----------------
__device__ __forceinline__ unsigned f2tf32(float f) {
    unsigned r;
    asm("cvt.rna.tf32.f32 %0, %1;" : "=r"(r) : "f"(f));
    return r;
}

template <int BN, int SRC>   // SRC=0: A = Aext, SRC=1: A = g_o
__global__ __launch_bounds__(256) void gemm_tc_kernel(
    const float* __restrict__ Aext, const float* __restrict__ B)
{
    constexpr int WN = BN / 4;
    constexpr int NF = WN / 8;
    constexpr int BK = 32;

    __shared__ unsigned As[128][BK + 4];
    __shared__ unsigned Bs[BK][BN + 8];

    const float* A = (SRC == 0) ? Aext : g_o;
    int tid  = threadIdx.x;
    int warp = tid >> 5;
    int lane = tid & 31;
    int gid  = lane >> 2;
    int tig  = lane & 3;
    int warp_m = warp >> 2;
    int warp_n = warp & 3;
    int rowBase = blockIdx.y * 128;

    float acc[4][NF][4];
#pragma unroll
    for (int mf = 0; mf < 4; mf++)
#pragma unroll
        for (int nf = 0; nf < NF; nf++)
#pragma unroll
            for (int q = 0; q < 4; q++) acc[mf][nf][q] = 0.0f;

    for (int kc = 0; kc < 128; kc += BK) {
#pragma unroll
        for (int i = 0; i < 16; i++) {
            int idx = tid + i * 256;
            int m = idx >> 5;
            int k = idx & 31;
            int gm = rowBase + m;
            float v = (gm < N_NODES) ? A[(size_t)gm * 128 + kc + k] : 0.0f;
            As[m][k] = f2tf32(v);
        }
#pragma unroll
        for (int i = 0; i < (32 * BN) / 256; i++) {
            int idx = tid + i * 256;
            int k = idx / BN;
            int n = idx % BN;
            Bs[k][n] = f2tf32(B[(size_t)(kc + k) * BN + n]);
        }
        __syncthreads();

#pragma unroll
        for (int ks = 0; ks < BK / 8; ks++) {
            int k0 = ks * 8;
            unsigned a[4][4];
#pragma unroll
            for (int mf = 0; mf < 4; mf++) {
                int rb = warp_m * 64 + mf * 16;
                a[mf][0] = As[rb + gid][k0 + tig];
                a[mf][1] = As[rb + gid + 8][k0 + tig];
                a[mf][2] = As[rb + gid][k0 + tig + 4];
                a[mf][3] = As[rb + gid + 8][k0 + tig + 4];
            }
#pragma unroll
            for (int nf = 0; nf < NF; nf++) {
                int nb = warp_n * WN + nf * 8;
                unsigned b0 = Bs[k0 + tig][nb + gid];
                unsigned b1 = Bs[k0 + tig + 4][nb + gid];
#pragma unroll
                for (int mf = 0; mf < 4; mf++) {
                    asm volatile(
                        "mma.sync.aligned.m16n8k8.row.col.f32.tf32.tf32.f32 "
                        "{%0,%1,%2,%3}, {%4,%5,%6,%7}, {%8,%9}, {%0,%1,%2,%3};"
                        : "+f"(acc[mf][nf][0]), "+f"(acc[mf][nf][1]),
                          "+f"(acc[mf][nf][2]), "+f"(acc[mf][nf][3])
                        : "r"(a[mf][0]), "r"(a[mf][1]),
                          "r"(a[mf][2]), "r"(a[mf][3]),
                          "r"(b0), "r"(b1));
                }
            }
        }
        __syncthreads();
    }

#pragma unroll
    for (int mf = 0; mf < 4; mf++) {
        int r0 = rowBase + warp_m * 64 + mf * 16 + gid;
        int r1 = r0 + 8;
        float d0 = (r0 < N_NODES) ? g_dinv[r0] : 0.0f;
        float d1 = (r1 < N_NODES) ? g_dinv[r1] : 0.0f;
#pragma unroll
        for (int nf = 0; nf < NF; nf++) {
            int nc = warp_n * WN + nf * 8 + tig * 2;
            if (r0 < N_NODES) {
                __half2 hv = __floats2half2_rn(acc[mf][nf][0] * d0, acc[mf][nf][1] * d0);
                *(__half2*)&g_h16[(size_t)r0 * BN + nc] = hv;
            }
            if (r1 < N_NODES) {
                __half2 hv = __floats2half2_rn(acc[mf][nf][2] * d1, acc[mf][nf][3] * d1);
                *(__half2*)&g_h16[(size_t)r1 * BN + nc] = hv;
            }
        }
    }
}

// ---------------- CSR aggregate, DIM=128: 16 lanes per node, uint4 (LDG.128) gathers --------
// o[c] = relu?( dinv[c] * (hs[c] + sum_r hs[r]) + b ), hs fp16 prescaled, accum fp32.
#define ACC8(U)  do {                                                   \
    float2 _p;                                                          \
    _p = __half22float2(*(const __half2*)&(U).x); a0 += _p.x; a1 += _p.y; \
    _p = __half22float2(*(const __half2*)&(U).y); a2 += _p.x; a3 += _p.y; \
    _p = __half22float2(*(const __half2*)&(U).z); a4 += _p.x; a5 += _p.y; \
    _p = __half22float2(*(const __half2*)&(U).w); a6 += _p.x; a7 += _p.y; \
} while (0)

template <bool RELU>
__global__ __launch_bounds__(256) void agg128_kernel(const float* __restrict__ b)
{
    int gt = blockIdx.x * 256 + threadIdx.x;
    int c = gt >> 4;               // 16 lanes per node
    int sl = threadIdx.x & 15;     // sub-lane: features 8*sl .. 8*sl+7
    if (c >= N_NODES) return;

    const uint4* hs = (const uint4*)g_h16;   // 16 uint4 per 128-dim row

    uint4 u = hs[(size_t)c * 16 + sl];
    float a0, a1, a2, a3, a4, a5, a6, a7;
    {
        float2 p;
        p = __half22float2(*(const __half2*)&u.x); a0 = p.x; a1 = p.y;
        p = __half22float2(*(const __half2*)&u.y); a2 = p.x; a3 = p.y;
        p = __half22float2(*(const __half2*)&u.z); a4 = p.x; a5 = p.y;
        p = __half22float2(*(const __half2*)&u.w); a6 = p.x; a7 = p.y;
    }

    int s = g_off[c], e = g_off[c + 1];
    int i = s;
    for (; i + 4 <= e; i += 4) {
        int r0 = g_adj[i], r1 = g_adj[i + 1], r2 = g_adj[i + 2], r3 = g_adj[i + 3];
        uint4 u0 = hs[(size_t)r0 * 16 + sl];
        uint4 u1 = hs[(size_t)r1 * 16 + sl];
        uint4 u2 = hs[(size_t)r2 * 16 + sl];
        uint4 u3 = hs[(size_t)r3 * 16 + sl];
        ACC8(u0); ACC8(u1); ACC8(u2); ACC8(u3);
    }
    for (; i < e; i++) {
        uint4 uv = hs[(size_t)g_adj[i] * 16 + sl];
        ACC8(uv);
    }

    float d = g_dinv[c];
    const float4* b4 = (const float4*)b;
    float4 bb0 = b4[sl * 2], bb1 = b4[sl * 2 + 1];
    float4 r0v, r1v;
    r0v.x = a0 * d + bb0.x;  r0v.y = a1 * d + bb0.y;
    r0v.z = a2 * d + bb0.z;  r0v.w = a3 * d + bb0.w;
    r1v.x = a4 * d + bb1.x;  r1v.y = a5 * d + bb1.y;
    r1v.z = a6 * d + bb1.z;  r1v.w = a7 * d + bb1.w;
    if (RELU) {
        r0v.x = fmaxf(r0v.x, 0.0f); r0v.y = fmaxf(r0v.y, 0.0f);
        r0v.z = fmaxf(r0v.z, 0.0f); r0v.w = fmaxf(r0v.w, 0.0f);
        r1v.x = fmaxf(r1v.x, 0.0f); r1v.y = fmaxf(r1v.y, 0.0f);
        r1v.z = fmaxf(r1v.z, 0.0f); r1v.w = fmaxf(r1v.w, 0.0f);
    }
    float4* o4 = (float4*)g_o;
    o4[(size_t)c * 32 + sl * 2]     = r0v;
    o4[(size_t)c * 32 + sl * 2 + 1] = r1v;
}

// DIM=64 final layer: 8 lanes per node (row = 128B = 8 uint4), writes d_out fp32.
__global__ __launch_bounds__(256) void agg64_kernel(float* __restrict__ out,
                                                    const float* __restrict__ b)
{
    int gt = blockIdx.x * 256 + threadIdx.x;
    int c = gt >> 3;               // 8 lanes per node
    int sl = threadIdx.x & 7;      // features 8*sl .. 8*sl+7
    if (c >= N_NODES) return;

    const uint4* hs = (const uint4*)g_h16;   // 8 uint4 per 64-dim row

    uint4 u = hs[(size_t)c * 8 + sl];
    float a0, a1, a2, a3, a4, a5, a6, a7;
    {
        float2 p;
        p = __half22float2(*(const __half2*)&u.x); a0 = p.x; a1 = p.y;
        p = __half22float2(*(const __half2*)&u.y); a2 = p.x; a3 = p.y;
        p = __half22float2(*(const __half2*)&u.z); a4 = p.x; a5 = p.y;
        p = __half22float2(*(const __half2*)&u.w); a6 = p.x; a7 = p.y;
    }

    int s = g_off[c], e = g_off[c + 1];
    int i = s;
    for (; i + 4 <= e; i += 4) {
        int r0 = g_adj[i], r1 = g_adj[i + 1], r2 = g_adj[i + 2], r3 = g_adj[i + 3];
        uint4 u0 = hs[(size_t)r0 * 8 + sl];
        uint4 u1 = hs[(size_t)r1 * 8 + sl];
        uint4 u2 = hs[(size_t)r2 * 8 + sl];
        uint4 u3 = hs[(size_t)r3 * 8 + sl];
        ACC8(u0); ACC8(u1); ACC8(u2); ACC8(u3);
    }
    for (; i < e; i++) {
        uint4 uv = hs[(size_t)g_adj[i] * 8 + sl];
        ACC8(uv);
    }

    float d = g_dinv[c];
    const float4* b4 = (const float4*)b;
    float4 bb0 = b4[sl * 2], bb1 = b4[sl * 2 + 1];
    float4 r0v, r1v;
    r0v.x = a0 * d + bb0.x;  r0v.y = a1 * d + bb0.y;
    r0v.z = a2 * d + bb0.z;  r0v.w = a3 * d + bb0.w;
    r1v.x = a4 * d + bb1.x;  r1v.y = a5 * d + bb1.y;
    r1v.z = a6 * d + bb1.z;  r1v.w = a7 * d + bb1.w;
    float4* o4 = (float4*)out;
    o4[(size_t)c * 16 + sl * 2]     = r0v;
    o4[(size_t)c * 16 + sl * 2 + 1] = r1v;
}

// ---------------- launch ----------------
extern "C" void kernel_launch(void* const* d_in, const int* in_sizes, int n_in,
                              void* d_out, int out_size)
{
    const float* x      = (const float*)d_in[0];
    const int*   ei_raw = (const int*)d_in[1];
    const float* W1 = (const float*)d_in[2];
    const float* b1 = (const float*)d_in[3];
    const float* W2 = (const float*)d_in[4];
    const float* b2 = (const float*)d_in[5];
    const float* W3 = (const float*)d_in[6];
    const float* b3 = (const float*)d_in[7];
    float* out = (float*)d_out;

    // ---- CSR build + normalization (5 launches) ----
    detect_zero_kernel<<<NB, 256>>>(ei_raw);
    count_kernel<<<(N_EDGES + 255) / 256, 256>>>(ei_raw);
    scanA_kernel<<<NB, 256>>>();
    scanBC_kernel<<<NB, 256>>>();
    fill_kernel<<<(N_EDGES + 255) / 256, 256>>>(ei_raw);

    const int gemmRows = (N_NODES + 127) / 128;               // 391
    const int agg128Grid = (N_NODES * 16 + 255) / 256;        // 16 lanes/node
    const int agg64Grid  = (N_NODES * 8 + 255) / 256;         // 8 lanes/node

    // ---- layer 1 ----
    gemm_tc_kernel<128, 0><<<dim3(1, gemmRows), 256>>>(x, W1);
    agg128_kernel<true><<<agg128Grid, 256>>>(b1);

    // ---- layer 2 ----
    gemm_tc_kernel<128, 1><<<dim3(1, gemmRows), 256>>>(nullptr, W2);
    agg128_kernel<true><<<agg128Grid, 256>>>(b2);

    // ---- layer 3 (dim 64 -> d_out) ----
    gemm_tc_kernel<64, 1><<<dim3(1, gemmRows), 256>>>(nullptr, W3);
    agg64_kernel<<<agg64Grid, 256>>>(out, b3);
}

// round 12
// speedup vs baseline: 3.2833x; 1.0407x over previous
#include <cuda_runtime.h>
#include <cuda_fp16.h>
#include <stdint.h>

#define N_NODES 50000
#define N_EDGES 800000
#define NB      208            // scan blocks: 208*256 = 53248 >= N_NODES

// ---------------- scratch (allocation-free: __device__ globals) ----------------
__device__ __align__(16) float  g_dinv[N_NODES];
__device__ __align__(16) __half g_h16[N_NODES * 128]; // GEMM out, dinv-prescaled, fp16
__device__ __align__(16) float  g_o[N_NODES * 128];   // layer output (fp32, next GEMM input)
__device__ int g_adj[N_EDGES];        // CSR: source nodes grouped by dest
__device__ int g_off[N_NODES + 1];    // CSR offsets
__device__ int g_cur[N_NODES];        // fill cursors
__device__ int g_degi[N_NODES];       // in-degree (edges only)
__device__ int g_bsum[NB];            // per-block degree sums
__device__ int g_is64;

// ---------------- detect dtype + zero degrees (one launch) ----------------
__global__ void detect_zero_kernel(const int* __restrict__ ei_raw) {
    int i = blockIdx.x * 256 + threadIdx.x;
    if (i < N_NODES) g_degi[i] = 0;
    if (blockIdx.x == 0) {
        __shared__ int any;
        if (threadIdx.x == 0) any = 0;
        __syncthreads();
        int nz = 0;
        for (int j = threadIdx.x; j < 1024; j += 256)
            nz |= ei_raw[2 * j + 1];
        if (nz) atomicOr(&any, 1);
        __syncthreads();
        if (threadIdx.x == 0) g_is64 = (any == 0);
    }
}

// degree count straight from raw edge buffer
__global__ void count_kernel(const int* __restrict__ ei_raw) {
    int i = blockIdx.x * blockDim.x + threadIdx.x;
    if (i >= N_EDGES) return;
    int c = g_is64 ? ei_raw[2 * (N_EDGES + i)] : ei_raw[N_EDGES + i];
    atomicAdd(&g_degi[c], 1);
}

// dinv from degree counts (so gemm1 can start before the scan chain)
__global__ void dinv_kernel() {
    int i = blockIdx.x * 256 + threadIdx.x;
    if (i < N_NODES) g_dinv[i] = rsqrtf((float)(1 + g_degi[i]));
}

// ---------------- scan phase A: per-block degree sums ----------------
__global__ __launch_bounds__(256) void scanA_kernel() {
    __shared__ int sh[256];
    int i = blockIdx.x * 256 + threadIdx.x;
    int v = (i < N_NODES) ? g_degi[i] : 0;
    sh[threadIdx.x] = v;
    __syncthreads();
    for (int o = 128; o > 0; o >>= 1) {
        if (threadIdx.x < o) sh[threadIdx.x] += sh[threadIdx.x + o];
        __syncthreads();
    }
    if (threadIdx.x == 0) g_bsum[blockIdx.x] = sh[0];
}

// ---------------- scan phase B+C merged: offsets + cursors ----------------
__global__ __launch_bounds__(256) void scanBC_kernel() {
    __shared__ int pre[256];
    __shared__ int sh[256];
    int t = threadIdx.x;

    pre[t] = (t < NB && t < blockIdx.x) ? g_bsum[t] : 0;
    __syncthreads();
    for (int o = 128; o > 0; o >>= 1) {
        if (t < o) pre[t] += pre[t + o];
        __syncthreads();
    }
    int bpref = pre[0];

    int i = blockIdx.x * 256 + t;
    int d = (i < N_NODES) ? g_degi[i] : 0;
    sh[t] = d;
    __syncthreads();
    for (int o = 1; o < 256; o <<= 1) {
        int x = sh[t];
        int a = (t >= o) ? sh[t - o] : 0;
        __syncthreads();
        sh[t] = x + a;
        __syncthreads();
    }
    if (i < N_NODES) {
        int excl = sh[t] - d + bpref;
        g_off[i] = excl;
        g_cur[i] = excl;
    }
    if (i == 0) g_off[N_NODES] = N_EDGES;
}

// fill CSR straight from raw edge buffer
__global__ void fill_kernel(const int* __restrict__ ei_raw) {
    int i = blockIdx.x * blockDim.x + threadIdx.x;
    if (i >= N_EDGES) return;
    int r, c;
    if (g_is64) {
        r = ei_raw[2 * i];
        c = ei_raw[2 * (N_EDGES + i)];
    } else {
        r = ei_raw[i];
        c = ei_raw[N_EDGES + i];
    }
    int pos = atomicAdd(&g_cur[c], 1);
    g_adj[pos] = r;
}

// ---------------- tf32 tensor-core GEMM: g_h16[m,:] = fp16( dinv[m]*(A @ B)[m,:] ) ----------------
__device__ __forceinline__ unsigned f2tf32(float f) {
    unsigned r;
    asm("cvt.rna.tf32.f32 %0, %1;" : "=r"(r) : "f"(f));
    return r;
}

template <int BN, int SRC>   // SRC=0: A = Aext, SRC=1: A = g_o
__global__ __launch_bounds__(256) void gemm_tc_kernel(
    const float* __restrict__ Aext, const float* __restrict__ B)
{
    constexpr int WN = BN / 4;
    constexpr int NF = WN / 8;
    constexpr int BK = 32;

    __shared__ unsigned As[128][BK + 4];
    __shared__ unsigned Bs[BK][BN + 8];

    const float* A = (SRC == 0) ? Aext : g_o;
    int tid  = threadIdx.x;
    int warp = tid >> 5;
    int lane = tid & 31;
    int gid  = lane >> 2;
    int tig  = lane & 3;
    int warp_m = warp >> 2;
    int warp_n = warp & 3;
    int rowBase = blockIdx.y * 128;

    float acc[4][NF][4];
#pragma unroll
    for (int mf = 0; mf < 4; mf++)
#pragma unroll
        for (int nf = 0; nf < NF; nf++)
#pragma unroll
            for (int q = 0; q < 4; q++) acc[mf][nf][q] = 0.0f;

    for (int kc = 0; kc < 128; kc += BK) {
#pragma unroll
        for (int i = 0; i < 16; i++) {
            int idx = tid + i * 256;
            int m = idx >> 5;
            int k = idx & 31;
            int gm = rowBase + m;
            float v = (gm < N_NODES) ? A[(size_t)gm * 128 + kc + k] : 0.0f;
            As[m][k] = f2tf32(v);
        }
#pragma unroll
        for (int i = 0; i < (32 * BN) / 256; i++) {
            int idx = tid + i * 256;
            int k = idx / BN;
            int n = idx % BN;
            Bs[k][n] = f2tf32(B[(size_t)(kc + k) * BN + n]);
        }
        __syncthreads();

#pragma unroll
        for (int ks = 0; ks < BK / 8; ks++) {
            int k0 = ks * 8;
            unsigned a[4][4];
#pragma unroll
            for (int mf = 0; mf < 4; mf++) {
                int rb = warp_m * 64 + mf * 16;
                a[mf][0] = As[rb + gid][k0 + tig];
                a[mf][1] = As[rb + gid + 8][k0 + tig];
                a[mf][2] = As[rb + gid][k0 + tig + 4];
                a[mf][3] = As[rb + gid + 8][k0 + tig + 4];
            }
#pragma unroll
            for (int nf = 0; nf < NF; nf++) {
                int nb = warp_n * WN + nf * 8;
                unsigned b0 = Bs[k0 + tig][nb + gid];
                unsigned b1 = Bs[k0 + tig + 4][nb + gid];
#pragma unroll
                for (int mf = 0; mf < 4; mf++) {
                    asm volatile(
                        "mma.sync.aligned.m16n8k8.row.col.f32.tf32.tf32.f32 "
                        "{%0,%1,%2,%3}, {%4,%5,%6,%7}, {%8,%9}, {%0,%1,%2,%3};"
                        : "+f"(acc[mf][nf][0]), "+f"(acc[mf][nf][1]),
                          "+f"(acc[mf][nf][2]), "+f"(acc[mf][nf][3])
                        : "r"(a[mf][0]), "r"(a[mf][1]),
                          "r"(a[mf][2]), "r"(a[mf][3]),
                          "r"(b0), "r"(b1));
                }
            }
        }
        __syncthreads();
    }

#pragma unroll
    for (int mf = 0; mf < 4; mf++) {
        int r0 = rowBase + warp_m * 64 + mf * 16 + gid;
        int r1 = r0 + 8;
        float d0 = (r0 < N_NODES) ? g_dinv[r0] : 0.0f;
        float d1 = (r1 < N_NODES) ? g_dinv[r1] : 0.0f;
#pragma unroll
        for (int nf = 0; nf < NF; nf++) {
            int nc = warp_n * WN + nf * 8 + tig * 2;
            if (r0 < N_NODES) {
                __half2 hv = __floats2half2_rn(acc[mf][nf][0] * d0, acc[mf][nf][1] * d0);
                *(__half2*)&g_h16[(size_t)r0 * BN + nc] = hv;
            }
            if (r1 < N_NODES) {
                __half2 hv = __floats2half2_rn(acc[mf][nf][2] * d1, acc[mf][nf][3] * d1);
                *(__half2*)&g_h16[(size_t)r1 * BN + nc] = hv;
            }
        }
    }
}

// ---------------- CSR aggregate, DIM=128: 16 lanes/node, uint4 gathers, 8-deep MLP -------
#define ACC8(U)  do {                                                   \
    float2 _p;                                                          \
    _p = __half22float2(*(const __half2*)&(U).x); a0 += _p.x; a1 += _p.y; \
    _p = __half22float2(*(const __half2*)&(U).y); a2 += _p.x; a3 += _p.y; \
    _p = __half22float2(*(const __half2*)&(U).z); a4 += _p.x; a5 += _p.y; \
    _p = __half22float2(*(const __half2*)&(U).w); a6 += _p.x; a7 += _p.y; \
} while (0)

template <bool RELU>
__global__ __launch_bounds__(256) void agg128_kernel(const float* __restrict__ b)
{
    int gt = blockIdx.x * 256 + threadIdx.x;
    int c = gt >> 4;               // 16 lanes per node
    int sl = threadIdx.x & 15;     // features 8*sl .. 8*sl+7
    if (c >= N_NODES) return;

    const uint4* hs = (const uint4*)g_h16;   // 16 uint4 per 128-dim row

    uint4 u = hs[(size_t)c * 16 + sl];
    float a0, a1, a2, a3, a4, a5, a6, a7;
    {
        float2 p;
        p = __half22float2(*(const __half2*)&u.x); a0 = p.x; a1 = p.y;
        p = __half22float2(*(const __half2*)&u.y); a2 = p.x; a3 = p.y;
        p = __half22float2(*(const __half2*)&u.z); a4 = p.x; a5 = p.y;
        p = __half22float2(*(const __half2*)&u.w); a6 = p.x; a7 = p.y;
    }

    int s = g_off[c], e = g_off[c + 1];
    int i = s;
    for (; i + 8 <= e; i += 8) {
        int r0 = g_adj[i],     r1 = g_adj[i + 1], r2 = g_adj[i + 2], r3 = g_adj[i + 3];
        int r4 = g_adj[i + 4], r5 = g_adj[i + 5], r6 = g_adj[i + 6], r7 = g_adj[i + 7];
        uint4 u0 = hs[(size_t)r0 * 16 + sl];
        uint4 u1 = hs[(size_t)r1 * 16 + sl];
        uint4 u2 = hs[(size_t)r2 * 16 + sl];
        uint4 u3 = hs[(size_t)r3 * 16 + sl];
        uint4 u4 = hs[(size_t)r4 * 16 + sl];
        uint4 u5 = hs[(size_t)r5 * 16 + sl];
        uint4 u6 = hs[(size_t)r6 * 16 + sl];
        uint4 u7 = hs[(size_t)r7 * 16 + sl];
        ACC8(u0); ACC8(u1); ACC8(u2); ACC8(u3);
        ACC8(u4); ACC8(u5); ACC8(u6); ACC8(u7);
    }
    for (; i < e; i++) {
        uint4 uv = hs[(size_t)g_adj[i] * 16 + sl];
        ACC8(uv);
    }

    float d = g_dinv[c];
    const float4* b4 = (const float4*)b;
    float4 bb0 = b4[sl * 2], bb1 = b4[sl * 2 + 1];
    float4 r0v, r1v;
    r0v.x = a0 * d + bb0.x;  r0v.y = a1 * d + bb0.y;
    r0v.z = a2 * d + bb0.z;  r0v.w = a3 * d + bb0.w;
    r1v.x = a4 * d + bb1.x;  r1v.y = a5 * d + bb1.y;
    r1v.z = a6 * d + bb1.z;  r1v.w = a7 * d + bb1.w;
    if (RELU) {
        r0v.x = fmaxf(r0v.x, 0.0f); r0v.y = fmaxf(r0v.y, 0.0f);
        r0v.z = fmaxf(r0v.z, 0.0f); r0v.w = fmaxf(r0v.w, 0.0f);
        r1v.x = fmaxf(r1v.x, 0.0f); r1v.y = fmaxf(r1v.y, 0.0f);
        r1v.z = fmaxf(r1v.z, 0.0f); r1v.w = fmaxf(r1v.w, 0.0f);
    }
    float4* o4 = (float4*)g_o;
    o4[(size_t)c * 32 + sl * 2]     = r0v;
    o4[(size_t)c * 32 + sl * 2 + 1] = r1v;
}

// DIM=64 final layer: 8 lanes per node, 8-deep MLP, writes d_out fp32.
__global__ __launch_bounds__(256) void agg64_kernel(float* __restrict__ out,
                                                    const float* __restrict__ b)
{
    int gt = blockIdx.x * 256 + threadIdx.x;
    int c = gt >> 3;               // 8 lanes per node
    int sl = threadIdx.x & 7;      // features 8*sl .. 8*sl+7
    if (c >= N_NODES) return;

    const uint4* hs = (const uint4*)g_h16;   // 8 uint4 per 64-dim row

    uint4 u = hs[(size_t)c * 8 + sl];
    float a0, a1, a2, a3, a4, a5, a6, a7;
    {
        float2 p;
        p = __half22float2(*(const __half2*)&u.x); a0 = p.x; a1 = p.y;
        p = __half22float2(*(const __half2*)&u.y); a2 = p.x; a3 = p.y;
        p = __half22float2(*(const __half2*)&u.z); a4 = p.x; a5 = p.y;
        p = __half22float2(*(const __half2*)&u.w); a6 = p.x; a7 = p.y;
    }

    int s = g_off[c], e = g_off[c + 1];
    int i = s;
    for (; i + 8 <= e; i += 8) {
        int r0 = g_adj[i],     r1 = g_adj[i + 1], r2 = g_adj[i + 2], r3 = g_adj[i + 3];
        int r4 = g_adj[i + 4], r5 = g_adj[i + 5], r6 = g_adj[i + 6], r7 = g_adj[i + 7];
        uint4 u0 = hs[(size_t)r0 * 8 + sl];
        uint4 u1 = hs[(size_t)r1 * 8 + sl];
        uint4 u2 = hs[(size_t)r2 * 8 + sl];
        uint4 u3 = hs[(size_t)r3 * 8 + sl];
        uint4 u4 = hs[(size_t)r4 * 8 + sl];
        uint4 u5 = hs[(size_t)r5 * 8 + sl];
        uint4 u6 = hs[(size_t)r6 * 8 + sl];
        uint4 u7 = hs[(size_t)r7 * 8 + sl];
        ACC8(u0); ACC8(u1); ACC8(u2); ACC8(u3);
        ACC8(u4); ACC8(u5); ACC8(u6); ACC8(u7);
    }
    for (; i < e; i++) {
        uint4 uv = hs[(size_t)g_adj[i] * 8 + sl];
        ACC8(uv);
    }

    float d = g_dinv[c];
    const float4* b4 = (const float4*)b;
    float4 bb0 = b4[sl * 2], bb1 = b4[sl * 2 + 1];
    float4 r0v, r1v;
    r0v.x = a0 * d + bb0.x;  r0v.y = a1 * d + bb0.y;
    r0v.z = a2 * d + bb0.z;  r0v.w = a3 * d + bb0.w;
    r1v.x = a4 * d + bb1.x;  r1v.y = a5 * d + bb1.y;
    r1v.z = a6 * d + bb1.z;  r1v.w = a7 * d + bb1.w;
    float4* o4 = (float4*)out;
    o4[(size_t)c * 16 + sl * 2]     = r0v;
    o4[(size_t)c * 16 + sl * 2 + 1] = r1v;
}

// ---------------- launch ----------------
extern "C" void kernel_launch(void* const* d_in, const int* in_sizes, int n_in,
                              void* d_out, int out_size)
{
    const float* x      = (const float*)d_in[0];
    const int*   ei_raw = (const int*)d_in[1];
    const float* W1 = (const float*)d_in[2];
    const float* b1 = (const float*)d_in[3];
    const float* W2 = (const float*)d_in[4];
    const float* b2 = (const float*)d_in[5];
    const float* W3 = (const float*)d_in[6];
    const float* b3 = (const float*)d_in[7];
    float* out = (float*)d_out;

    // side stream + events, created once on the uncaptured correctness call
    static cudaStream_t s2 = nullptr;
    static cudaEvent_t  eA = nullptr, eB = nullptr;
    if (s2 == nullptr) {
        cudaStreamCreateWithFlags(&s2, cudaStreamNonBlocking);
        cudaEventCreateWithFlags(&eA, cudaEventDisableTiming);
        cudaEventCreateWithFlags(&eB, cudaEventDisableTiming);
    }

    const int gemmRows = (N_NODES + 127) / 128;               // 391
    const int agg128Grid = (N_NODES * 16 + 255) / 256;        // 16 lanes/node
    const int agg64Grid  = (N_NODES * 8 + 255) / 256;         // 8 lanes/node

    // ---- preamble: dtype + degrees + dinv (gemm1 dependency) ----
    detect_zero_kernel<<<NB, 256>>>(ei_raw);
    count_kernel<<<(N_EDGES + 255) / 256, 256>>>(ei_raw);
    dinv_kernel<<<NB, 256>>>();

    // fork: gemm1 on s2 overlaps scan/fill chain on main stream
    cudaEventRecord(eA, 0);
    cudaStreamWaitEvent(s2, eA, 0);
    gemm_tc_kernel<128, 0><<<dim3(1, gemmRows), 256, 0, s2>>>(x, W1);

    scanA_kernel<<<NB, 256>>>();
    scanBC_kernel<<<NB, 256>>>();
    fill_kernel<<<(N_EDGES + 255) / 256, 256>>>(ei_raw);

    cudaEventRecord(eB, s2);
    cudaStreamWaitEvent(0, eB, 0);

    // ---- layer 1 aggregate ----
    agg128_kernel<true><<<agg128Grid, 256>>>(b1);

    // ---- layer 2 ----
    gemm_tc_kernel<128, 1><<<dim3(1, gemmRows), 256>>>(nullptr, W2);
    agg128_kernel<true><<<agg128Grid, 256>>>(b2);

    // ---- layer 3 (dim 64 -> d_out) ----
    gemm_tc_kernel<64, 1><<<dim3(1, gemmRows), 256>>>(nullptr, W3);
    agg64_kernel<<<agg64Grid, 256>>>(out, b3);
}

// round 13
// speedup vs baseline: 3.5108x; 1.0693x over previous
#include <cuda_runtime.h>
#include <cuda_fp16.h>
#include <stdint.h>

#define N_NODES 50000
#define N_EDGES 800000
#define NB      208            // scan blocks: 208*256 = 53248 >= N_NODES

// ---------------- scratch (allocation-free: __device__ globals) ----------------
__device__ __align__(16) float  g_dinv[N_NODES];
__device__ __align__(16) __half g_h16[N_NODES * 128]; // GEMM out, dinv-prescaled, fp16
__device__ __align__(16) __half g_o16[N_NODES * 128]; // layer output (fp16, next GEMM A)
__device__ int g_adj[N_EDGES];        // CSR: source nodes grouped by dest
__device__ int g_off[N_NODES + 1];    // CSR offsets
__device__ int g_cur[N_NODES];        // fill cursors
__device__ int g_degi[N_NODES];       // in-degree (edges only)
__device__ int g_bsum[NB];            // per-block degree sums
__device__ int g_is64;

// ---------------- detect dtype + zero degrees (one launch) ----------------
__global__ void detect_zero_kernel(const int* __restrict__ ei_raw) {
    int i = blockIdx.x * 256 + threadIdx.x;
    if (i < N_NODES) g_degi[i] = 0;
    if (blockIdx.x == 0) {
        __shared__ int any;
        if (threadIdx.x == 0) any = 0;
        __syncthreads();
        int nz = 0;
        for (int j = threadIdx.x; j < 1024; j += 256)
            nz |= ei_raw[2 * j + 1];
        if (nz) atomicOr(&any, 1);
        __syncthreads();
        if (threadIdx.x == 0) g_is64 = (any == 0);
    }
}

__global__ void count_kernel(const int* __restrict__ ei_raw) {
    int i = blockIdx.x * blockDim.x + threadIdx.x;
    if (i >= N_EDGES) return;
    int c = g_is64 ? ei_raw[2 * (N_EDGES + i)] : ei_raw[N_EDGES + i];
    atomicAdd(&g_degi[c], 1);
}

__global__ void dinv_kernel() {
    int i = blockIdx.x * 256 + threadIdx.x;
    if (i < N_NODES) g_dinv[i] = rsqrtf((float)(1 + g_degi[i]));
}

// ---------------- scan phase A: per-block degree sums ----------------
__global__ __launch_bounds__(256) void scanA_kernel() {
    __shared__ int sh[256];
    int i = blockIdx.x * 256 + threadIdx.x;
    int v = (i < N_NODES) ? g_degi[i] : 0;
    sh[threadIdx.x] = v;
    __syncthreads();
    for (int o = 128; o > 0; o >>= 1) {
        if (threadIdx.x < o) sh[threadIdx.x] += sh[threadIdx.x + o];
        __syncthreads();
    }
    if (threadIdx.x == 0) g_bsum[blockIdx.x] = sh[0];
}

// ---------------- scan phase B+C merged: offsets + cursors ----------------
__global__ __launch_bounds__(256) void scanBC_kernel() {
    __shared__ int pre[256];
    __shared__ int sh[256];
    int t = threadIdx.x;

    pre[t] = (t < NB && t < blockIdx.x) ? g_bsum[t] : 0;
    __syncthreads();
    for (int o = 128; o > 0; o >>= 1) {
        if (t < o) pre[t] += pre[t + o];
        __syncthreads();
    }
    int bpref = pre[0];

    int i = blockIdx.x * 256 + t;
    int d = (i < N_NODES) ? g_degi[i] : 0;
    sh[t] = d;
    __syncthreads();
    for (int o = 1; o < 256; o <<= 1) {
        int x = sh[t];
        int a = (t >= o) ? sh[t - o] : 0;
        __syncthreads();
        sh[t] = x + a;
        __syncthreads();
    }
    if (i < N_NODES) {
        int excl = sh[t] - d + bpref;
        g_off[i] = excl;
        g_cur[i] = excl;
    }
    if (i == 0) g_off[N_NODES] = N_EDGES;
}

__global__ void fill_kernel(const int* __restrict__ ei_raw) {
    int i = blockIdx.x * blockDim.x + threadIdx.x;
    if (i >= N_EDGES) return;
    int r, c;
    if (g_is64) {
        r = ei_raw[2 * i];
        c = ei_raw[2 * (N_EDGES + i)];
    } else {
        r = ei_raw[i];
        c = ei_raw[N_EDGES + i];
    }
    int pos = atomicAdd(&g_cur[c], 1);
    g_adj[pos] = r;
}

// ---------------- fp16 tensor-core GEMM: g_h16[m,:] = fp16( dinv[m]*(A @ B)[m,:] ) ----------
// mma.sync.aligned.m16n8k16.row.col.f32.f16.f16.f32
// Block tile 128 x BN, 8 warps (2M x 4N), warp tile 64 x (BN/4).
// A staged as half [128][BK+8]; B staged TRANSPOSED as half [BN][BK+8] (n-major).

template <int BN, int SRC>   // SRC=0: A = Aext (fp32), SRC=1: A = g_o16 (fp16)
__global__ __launch_bounds__(256) void gemm_tc_kernel(
    const float* __restrict__ Aext, const float* __restrict__ B)
{
    constexpr int WN = BN / 4;     // warp N tile (32 or 16)
    constexpr int NF = WN / 8;     // n fragments per warp (4 or 2)
    constexpr int BK = 32;

    __shared__ __half Ah[128][BK + 8];   // row stride 40 halfs = 20 words: conflict-free frags
    __shared__ __half Bh[BN][BK + 8];    // [n][k]

    int tid  = threadIdx.x;
    int warp = tid >> 5;
    int lane = tid & 31;
    int gid  = lane >> 2;          // 0..7
    int tig  = lane & 3;           // 0..3
    int warp_m = warp >> 2;        // 0..1
    int warp_n = warp & 3;         // 0..3
    int rowBase = blockIdx.y * 128;

    float acc[4][NF][4];
#pragma unroll
    for (int mf = 0; mf < 4; mf++)
#pragma unroll
        for (int nf = 0; nf < NF; nf++)
#pragma unroll
            for (int q = 0; q < 4; q++) acc[mf][nf][q] = 0.0f;

    for (int kc = 0; kc < 128; kc += BK) {
        // ---- stage A tile 128 x 32 halfs (2048 half2, 8 per thread) ----
#pragma unroll
        for (int i = 0; i < 8; i++) {
            int idx = tid + i * 256;
            int m  = idx >> 4;          // 16 half2 per row
            int k2 = idx & 15;
            int gm = rowBase + m;
            if (SRC == 0) {
                float2 v = (gm < N_NODES)
                    ? *(const float2*)&Aext[(size_t)gm * 128 + kc + 2 * k2]
                    : make_float2(0.0f, 0.0f);
                *(__half2*)&Ah[m][2 * k2] = __float22half2_rn(v);
            } else {
                unsigned v = (gm < N_NODES)
                    ? *(const unsigned*)&g_o16[(size_t)gm * 128 + kc + 2 * k2]
                    : 0u;
                *(unsigned*)&Ah[m][2 * k2] = v;
            }
        }
        // ---- stage B tile transposed: Bh[n][k] = W[kc+k][n] ----
#pragma unroll
        for (int i = 0; i < (32 * BN) / 256; i++) {
            int idx = tid + i * 256;
            int k = idx / BN;
            int n = idx % BN;
            Bh[n][k] = __float2half(B[(size_t)(kc + k) * BN + n]);
        }
        __syncthreads();

#pragma unroll
        for (int ks = 0; ks < 2; ks++) {
            int k0 = ks * 16;
            unsigned a[4][4];
#pragma unroll
            for (int mf = 0; mf < 4; mf++) {
                int rb = warp_m * 64 + mf * 16;
                a[mf][0] = *(const unsigned*)&Ah[rb + gid][k0 + 2 * tig];
                a[mf][1] = *(const unsigned*)&Ah[rb + gid + 8][k0 + 2 * tig];
                a[mf][2] = *(const unsigned*)&Ah[rb + gid][k0 + 2 * tig + 8];
                a[mf][3] = *(const unsigned*)&Ah[rb + gid + 8][k0 + 2 * tig + 8];
            }
#pragma unroll
            for (int nf = 0; nf < NF; nf++) {
                int nb = warp_n * WN + nf * 8;
                unsigned b0 = *(const unsigned*)&Bh[nb + gid][k0 + 2 * tig];
                unsigned b1 = *(const unsigned*)&Bh[nb + gid][k0 + 2 * tig + 8];
#pragma unroll
                for (int mf = 0; mf < 4; mf++) {
                    asm volatile(
                        "mma.sync.aligned.m16n8k16.row.col.f32.f16.f16.f32 "
                        "{%0,%1,%2,%3}, {%4,%5,%6,%7}, {%8,%9}, {%0,%1,%2,%3};"
                        : "+f"(acc[mf][nf][0]), "+f"(acc[mf][nf][1]),
                          "+f"(acc[mf][nf][2]), "+f"(acc[mf][nf][3])
                        : "r"(a[mf][0]), "r"(a[mf][1]),
                          "r"(a[mf][2]), "r"(a[mf][3]),
                          "r"(b0), "r"(b1));
                }
            }
        }
        __syncthreads();
    }

    // epilogue: scale rows by dinv, pack to half2, store to g_h16
#pragma unroll
    for (int mf = 0; mf < 4; mf++) {
        int r0 = rowBase + warp_m * 64 + mf * 16 + gid;
        int r1 = r0 + 8;
        float d0 = (r0 < N_NODES) ? g_dinv[r0] : 0.0f;
        float d1 = (r1 < N_NODES) ? g_dinv[r1] : 0.0f;
#pragma unroll
        for (int nf = 0; nf < NF; nf++) {
            int nc = warp_n * WN + nf * 8 + tig * 2;
            if (r0 < N_NODES) {
                __half2 hv = __floats2half2_rn(acc[mf][nf][0] * d0, acc[mf][nf][1] * d0);
                *(__half2*)&g_h16[(size_t)r0 * BN + nc] = hv;
            }
            if (r1 < N_NODES) {
                __half2 hv = __floats2half2_rn(acc[mf][nf][2] * d1, acc[mf][nf][3] * d1);
                *(__half2*)&g_h16[(size_t)r1 * BN + nc] = hv;
            }
        }
    }
}

// ---------------- CSR aggregate, DIM=128: 16 lanes/node, uint4 gathers, 8-deep MLP -------
#define ACC8(U)  do {                                                   \
    float2 _p;                                                          \
    _p = __half22float2(*(const __half2*)&(U).x); a0 += _p.x; a1 += _p.y; \
    _p = __half22float2(*(const __half2*)&(U).y); a2 += _p.x; a3 += _p.y; \
    _p = __half22float2(*(const __half2*)&(U).z); a4 += _p.x; a5 += _p.y; \
    _p = __half22float2(*(const __half2*)&(U).w); a6 += _p.x; a7 += _p.y; \
} while (0)

template <bool RELU>
__global__ __launch_bounds__(256) void agg128_kernel(const float* __restrict__ b)
{
    int gt = blockIdx.x * 256 + threadIdx.x;
    int c = gt >> 4;               // 16 lanes per node
    int sl = threadIdx.x & 15;     // features 8*sl .. 8*sl+7
    if (c >= N_NODES) return;

    const uint4* hs = (const uint4*)g_h16;   // 16 uint4 per 128-dim row

    uint4 u = hs[(size_t)c * 16 + sl];
    float a0, a1, a2, a3, a4, a5, a6, a7;
    {
        float2 p;
        p = __half22float2(*(const __half2*)&u.x); a0 = p.x; a1 = p.y;
        p = __half22float2(*(const __half2*)&u.y); a2 = p.x; a3 = p.y;
        p = __half22float2(*(const __half2*)&u.z); a4 = p.x; a5 = p.y;
        p = __half22float2(*(const __half2*)&u.w); a6 = p.x; a7 = p.y;
    }

    int s = g_off[c], e = g_off[c + 1];
    int i = s;
    for (; i + 8 <= e; i += 8) {
        int r0 = g_adj[i],     r1 = g_adj[i + 1], r2 = g_adj[i + 2], r3 = g_adj[i + 3];
        int r4 = g_adj[i + 4], r5 = g_adj[i + 5], r6 = g_adj[i + 6], r7 = g_adj[i + 7];
        uint4 u0 = hs[(size_t)r0 * 16 + sl];
        uint4 u1 = hs[(size_t)r1 * 16 + sl];
        uint4 u2 = hs[(size_t)r2 * 16 + sl];
        uint4 u3 = hs[(size_t)r3 * 16 + sl];
        uint4 u4 = hs[(size_t)r4 * 16 + sl];
        uint4 u5 = hs[(size_t)r5 * 16 + sl];
        uint4 u6 = hs[(size_t)r6 * 16 + sl];
        uint4 u7 = hs[(size_t)r7 * 16 + sl];
        ACC8(u0); ACC8(u1); ACC8(u2); ACC8(u3);
        ACC8(u4); ACC8(u5); ACC8(u6); ACC8(u7);
    }
    for (; i < e; i++) {
        uint4 uv = hs[(size_t)g_adj[i] * 16 + sl];
        ACC8(uv);
    }

    float d = g_dinv[c];
    const float4* b4 = (const float4*)b;
    float4 bb0 = b4[sl * 2], bb1 = b4[sl * 2 + 1];
    float v0 = a0 * d + bb0.x, v1 = a1 * d + bb0.y;
    float v2 = a2 * d + bb0.z, v3 = a3 * d + bb0.w;
    float v4 = a4 * d + bb1.x, v5 = a5 * d + bb1.y;
    float v6 = a6 * d + bb1.z, v7 = a7 * d + bb1.w;
    if (RELU) {
        v0 = fmaxf(v0, 0.0f); v1 = fmaxf(v1, 0.0f);
        v2 = fmaxf(v2, 0.0f); v3 = fmaxf(v3, 0.0f);
        v4 = fmaxf(v4, 0.0f); v5 = fmaxf(v5, 0.0f);
        v6 = fmaxf(v6, 0.0f); v7 = fmaxf(v7, 0.0f);
    }
    // pack 8 halfs -> one uint4 store into g_o16
    __half2 h0 = __floats2half2_rn(v0, v1);
    __half2 h1 = __floats2half2_rn(v2, v3);
    __half2 h2 = __floats2half2_rn(v4, v5);
    __half2 h3 = __floats2half2_rn(v6, v7);
    uint4 w;
    w.x = *(unsigned*)&h0;  w.y = *(unsigned*)&h1;
    w.z = *(unsigned*)&h2;  w.w = *(unsigned*)&h3;
    ((uint4*)g_o16)[(size_t)c * 16 + sl] = w;
}

// DIM=64 final layer: 8 lanes per node, 8-deep MLP, writes d_out fp32.
__global__ __launch_bounds__(256) void agg64_kernel(float* __restrict__ out,
                                                    const float* __restrict__ b)
{
    int gt = blockIdx.x * 256 + threadIdx.x;
    int c = gt >> 3;               // 8 lanes per node
    int sl = threadIdx.x & 7;      // features 8*sl .. 8*sl+7
    if (c >= N_NODES) return;

    const uint4* hs = (const uint4*)g_h16;   // 8 uint4 per 64-dim row

    uint4 u = hs[(size_t)c * 8 + sl];
    float a0, a1, a2, a3, a4, a5, a6, a7;
    {
        float2 p;
        p = __half22float2(*(const __half2*)&u.x); a0 = p.x; a1 = p.y;
        p = __half22float2(*(const __half2*)&u.y); a2 = p.x; a3 = p.y;
        p = __half22float2(*(const __half2*)&u.z); a4 = p.x; a5 = p.y;
        p = __half22float2(*(const __half2*)&u.w); a6 = p.x; a7 = p.y;
    }

    int s = g_off[c], e = g_off[c + 1];
    int i = s;
    for (; i + 8 <= e; i += 8) {
        int r0 = g_adj[i],     r1 = g_adj[i + 1], r2 = g_adj[i + 2], r3 = g_adj[i + 3];
        int r4 = g_adj[i + 4], r5 = g_adj[i + 5], r6 = g_adj[i + 6], r7 = g_adj[i + 7];
        uint4 u0 = hs[(size_t)r0 * 8 + sl];
        uint4 u1 = hs[(size_t)r1 * 8 + sl];
        uint4 u2 = hs[(size_t)r2 * 8 + sl];
        uint4 u3 = hs[(size_t)r3 * 8 + sl];
        uint4 u4 = hs[(size_t)r4 * 8 + sl];
        uint4 u5 = hs[(size_t)r5 * 8 + sl];
        uint4 u6 = hs[(size_t)r6 * 8 + sl];
        uint4 u7 = hs[(size_t)r7 * 8 + sl];
        ACC8(u0); ACC8(u1); ACC8(u2); ACC8(u3);
        ACC8(u4); ACC8(u5); ACC8(u6); ACC8(u7);
    }
    for (; i < e; i++) {
        uint4 uv = hs[(size_t)g_adj[i] * 8 + sl];
        ACC8(uv);
    }

    float d = g_dinv[c];
    const float4* b4 = (const float4*)b;
    float4 bb0 = b4[sl * 2], bb1 = b4[sl * 2 + 1];
    float4 r0v, r1v;
    r0v.x = a0 * d + bb0.x;  r0v.y = a1 * d + bb0.y;
    r0v.z = a2 * d + bb0.z;  r0v.w = a3 * d + bb0.w;
    r1v.x = a4 * d + bb1.x;  r1v.y = a5 * d + bb1.y;
    r1v.z = a6 * d + bb1.z;  r1v.w = a7 * d + bb1.w;
    float4* o4 = (float4*)out;
    o4[(size_t)c * 16 + sl * 2]     = r0v;
    o4[(size_t)c * 16 + sl * 2 + 1] = r1v;
}

// ---------------- launch ----------------
extern "C" void kernel_launch(void* const* d_in, const int* in_sizes, int n_in,
                              void* d_out, int out_size)
{
    const float* x      = (const float*)d_in[0];
    const int*   ei_raw = (const int*)d_in[1];
    const float* W1 = (const float*)d_in[2];
    const float* b1 = (const float*)d_in[3];
    const float* W2 = (const float*)d_in[4];
    const float* b2 = (const float*)d_in[5];
    const float* W3 = (const float*)d_in[6];
    const float* b3 = (const float*)d_in[7];
    float* out = (float*)d_out;

    // side stream + events, created once on the uncaptured correctness call
    static cudaStream_t s2 = nullptr;
    static cudaEvent_t  eA = nullptr, eB = nullptr;
    if (s2 == nullptr) {
        cudaStreamCreateWithFlags(&s2, cudaStreamNonBlocking);
        cudaEventCreateWithFlags(&eA, cudaEventDisableTiming);
        cudaEventCreateWithFlags(&eB, cudaEventDisableTiming);
    }

    const int gemmRows = (N_NODES + 127) / 128;               // 391
    const int agg128Grid = (N_NODES * 16 + 255) / 256;        // 16 lanes/node
    const int agg64Grid  = (N_NODES * 8 + 255) / 256;         // 8 lanes/node

    // ---- preamble: dtype + degrees + dinv (gemm1 dependency) ----
    detect_zero_kernel<<<NB, 256>>>(ei_raw);
    count_kernel<<<(N_EDGES + 255) / 256, 256>>>(ei_raw);
    dinv_kernel<<<NB, 256>>>();

    // fork: gemm1 on s2 overlaps scan/fill chain on main stream
    cudaEventRecord(eA, 0);
    cudaStreamWaitEvent(s2, eA, 0);
    gemm_tc_kernel<128, 0><<<dim3(1, gemmRows), 256, 0, s2>>>(x, W1);

    scanA_kernel<<<NB, 256>>>();
    scanBC_kernel<<<NB, 256>>>();
    fill_kernel<<<(N_EDGES + 255) / 256, 256>>>(ei_raw);

    cudaEventRecord(eB, s2);
    cudaStreamWaitEvent(0, eB, 0);

    // ---- layer 1 aggregate ----
    agg128_kernel<true><<<agg128Grid, 256>>>(b1);

    // ---- layer 2 ----
    gemm_tc_kernel<128, 1><<<dim3(1, gemmRows), 256>>>(nullptr, W2);
    agg128_kernel<true><<<agg128Grid, 256>>>(b2);

    // ---- layer 3 (dim 64 -> d_out) ----
    gemm_tc_kernel<64, 1><<<dim3(1, gemmRows), 256>>>(nullptr, W3);
    agg64_kernel<<<agg64Grid, 256>>>(out, b3);
}

// round 14
// speedup vs baseline: 3.5672x; 1.0161x over previous
#include <cuda_runtime.h>
#include <cuda_fp16.h>
#include <stdint.h>

#define N_NODES 50000
#define N_EDGES 800000
#define NB      208            // scan blocks: 208*256 = 53248 >= N_NODES

// ---------------- scratch (allocation-free: __device__ globals) ----------------
__device__ __align__(16) float  g_dinv[N_NODES];
__device__ __align__(16) __half g_h16[N_NODES * 128]; // GEMM out, dinv-prescaled, fp16
__device__ __align__(16) __half g_o16[N_NODES * 128]; // layer output (fp16, next GEMM A)
__device__ int g_adj[N_EDGES];        // CSR: source nodes grouped by dest
__device__ int g_off[N_NODES + 1];    // CSR offsets
__device__ int g_cur[N_NODES];        // fill cursors
__device__ int g_degi[N_NODES];       // in-degree (edges only)
__device__ int g_bsum[NB];            // per-block degree sums
__device__ int g_is64;

// ---------------- detect dtype + zero degrees (one launch) ----------------
__global__ void detect_zero_kernel(const int* __restrict__ ei_raw) {
    int i = blockIdx.x * 256 + threadIdx.x;
    if (i < N_NODES) g_degi[i] = 0;
    if (blockIdx.x == 0) {
        __shared__ int any;
        if (threadIdx.x == 0) any = 0;
        __syncthreads();
        int nz = 0;
        for (int j = threadIdx.x; j < 1024; j += 256)
            nz |= ei_raw[2 * j + 1];
        if (nz) atomicOr(&any, 1);
        __syncthreads();
        if (threadIdx.x == 0) g_is64 = (any == 0);
    }
}

__global__ void count_kernel(const int* __restrict__ ei_raw) {
    int i = blockIdx.x * blockDim.x + threadIdx.x;
    if (i >= N_EDGES) return;
    int c = g_is64 ? ei_raw[2 * (N_EDGES + i)] : ei_raw[N_EDGES + i];
    atomicAdd(&g_degi[c], 1);
}

__global__ void dinv_kernel() {
    int i = blockIdx.x * 256 + threadIdx.x;
    if (i < N_NODES) g_dinv[i] = rsqrtf((float)(1 + g_degi[i]));
}

// ---------------- scan phase A: per-block degree sums ----------------
__global__ __launch_bounds__(256) void scanA_kernel() {
    __shared__ int sh[256];
    int i = blockIdx.x * 256 + threadIdx.x;
    int v = (i < N_NODES) ? g_degi[i] : 0;
    sh[threadIdx.x] = v;
    __syncthreads();
    for (int o = 128; o > 0; o >>= 1) {
        if (threadIdx.x < o) sh[threadIdx.x] += sh[threadIdx.x + o];
        __syncthreads();
    }
    if (threadIdx.x == 0) g_bsum[blockIdx.x] = sh[0];
}

// ---------------- scan phase B+C merged: offsets + cursors ----------------
__global__ __launch_bounds__(256) void scanBC_kernel() {
    __shared__ int pre[256];
    __shared__ int sh[256];
    int t = threadIdx.x;

    pre[t] = (t < NB && t < blockIdx.x) ? g_bsum[t] : 0;
    __syncthreads();
    for (int o = 128; o > 0; o >>= 1) {
        if (t < o) pre[t] += pre[t + o];
        __syncthreads();
    }
    int bpref = pre[0];

    int i = blockIdx.x * 256 + t;
    int d = (i < N_NODES) ? g_degi[i] : 0;
    sh[t] = d;
    __syncthreads();
    for (int o = 1; o < 256; o <<= 1) {
        int x = sh[t];
        int a = (t >= o) ? sh[t - o] : 0;
        __syncthreads();
        sh[t] = x + a;
        __syncthreads();
    }
    if (i < N_NODES) {
        int excl = sh[t] - d + bpref;
        g_off[i] = excl;
        g_cur[i] = excl;
    }
    if (i == 0) g_off[N_NODES] = N_EDGES;
}

__global__ void fill_kernel(const int* __restrict__ ei_raw) {
    int i = blockIdx.x * blockDim.x + threadIdx.x;
    if (i >= N_EDGES) return;
    int r, c;
    if (g_is64) {
        r = ei_raw[2 * i];
        c = ei_raw[2 * (N_EDGES + i)];
    } else {
        r = ei_raw[i];
        c = ei_raw[N_EDGES + i];
    }
    int pos = atomicAdd(&g_cur[c], 1);
    g_adj[pos] = r;
}

// ---------------- fp16 tensor-core GEMM: g_h16[m,:] = fp16( dinv[m]*(A @ B)[m,:] ) ----------
// mma.sync.aligned.m16n8k16.row.col.f32.f16.f16.f32
// Block tile 128 x BN, 8 warps (2M x 4N), warp tile 64 x (BN/4).
// __launch_bounds__(256, 2): cap regs at 128 so 2 CTAs/SM are resident.

template <int BN, int SRC>   // SRC=0: A = Aext (fp32), SRC=1: A = g_o16 (fp16)
__global__ __launch_bounds__(256, 2) void gemm_tc_kernel(
    const float* __restrict__ Aext, const float* __restrict__ B)
{
    constexpr int WN = BN / 4;     // warp N tile (32 or 16)
    constexpr int NF = WN / 8;     // n fragments per warp (4 or 2)
    constexpr int BK = 32;

    __shared__ __half Ah[128][BK + 8];   // row stride 40 halfs = 20 words: conflict-free frags
    __shared__ __half Bh[BN][BK + 8];    // [n][k]

    int tid  = threadIdx.x;
    int warp = tid >> 5;
    int lane = tid & 31;
    int gid  = lane >> 2;          // 0..7
    int tig  = lane & 3;           // 0..3
    int warp_m = warp >> 2;        // 0..1
    int warp_n = warp & 3;         // 0..3
    int rowBase = blockIdx.y * 128;

    float acc[4][NF][4];
#pragma unroll
    for (int mf = 0; mf < 4; mf++)
#pragma unroll
        for (int nf = 0; nf < NF; nf++)
#pragma unroll
            for (int q = 0; q < 4; q++) acc[mf][nf][q] = 0.0f;

    for (int kc = 0; kc < 128; kc += BK) {
        // ---- stage A tile 128 x 32 halfs (2048 half2, 8 per thread) ----
#pragma unroll
        for (int i = 0; i < 8; i++) {
            int idx = tid + i * 256;
            int m  = idx >> 4;          // 16 half2 per row
            int k2 = idx & 15;
            int gm = rowBase + m;
            if (SRC == 0) {
                float2 v = (gm < N_NODES)
                    ? *(const float2*)&Aext[(size_t)gm * 128 + kc + 2 * k2]
                    : make_float2(0.0f, 0.0f);
                *(__half2*)&Ah[m][2 * k2] = __float22half2_rn(v);
            } else {
                unsigned v = (gm < N_NODES)
                    ? *(const unsigned*)&g_o16[(size_t)gm * 128 + kc + 2 * k2]
                    : 0u;
                *(unsigned*)&Ah[m][2 * k2] = v;
            }
        }
        // ---- stage B tile transposed: Bh[n][k] = W[kc+k][n] ----
#pragma unroll
        for (int i = 0; i < (32 * BN) / 256; i++) {
            int idx = tid + i * 256;
            int k = idx / BN;
            int n = idx % BN;
            Bh[n][k] = __float2half(B[(size_t)(kc + k) * BN + n]);
        }
        __syncthreads();

#pragma unroll
        for (int ks = 0; ks < 2; ks++) {
            int k0 = ks * 16;
            unsigned a[4][4];
#pragma unroll
            for (int mf = 0; mf < 4; mf++) {
                int rb = warp_m * 64 + mf * 16;
                a[mf][0] = *(const unsigned*)&Ah[rb + gid][k0 + 2 * tig];
                a[mf][1] = *(const unsigned*)&Ah[rb + gid + 8][k0 + 2 * tig];
                a[mf][2] = *(const unsigned*)&Ah[rb + gid][k0 + 2 * tig + 8];
                a[mf][3] = *(const unsigned*)&Ah[rb + gid + 8][k0 + 2 * tig + 8];
            }
#pragma unroll
            for (int nf = 0; nf < NF; nf++) {
                int nb = warp_n * WN + nf * 8;
                unsigned b0 = *(const unsigned*)&Bh[nb + gid][k0 + 2 * tig];
                unsigned b1 = *(const unsigned*)&Bh[nb + gid][k0 + 2 * tig + 8];
#pragma unroll
                for (int mf = 0; mf < 4; mf++) {
                    asm volatile(
                        "mma.sync.aligned.m16n8k16.row.col.f32.f16.f16.f32 "
                        "{%0,%1,%2,%3}, {%4,%5,%6,%7}, {%8,%9}, {%0,%1,%2,%3};"
                        : "+f"(acc[mf][nf][0]), "+f"(acc[mf][nf][1]),
                          "+f"(acc[mf][nf][2]), "+f"(acc[mf][nf][3])
                        : "r"(a[mf][0]), "r"(a[mf][1]),
                          "r"(a[mf][2]), "r"(a[mf][3]),
                          "r"(b0), "r"(b1));
                }
            }
        }
        __syncthreads();
    }

    // epilogue: scale rows by dinv, pack to half2, store to g_h16
#pragma unroll
    for (int mf = 0; mf < 4; mf++) {
        int r0 = rowBase + warp_m * 64 + mf * 16 + gid;
        int r1 = r0 + 8;
        bool p0 = (r0 < N_NODES);
        bool p1 = (r1 < N_NODES);
        float d0 = p0 ? g_dinv[r0] : 0.0f;
        float d1 = p1 ? g_dinv[r1] : 0.0f;
#pragma unroll
        for (int nf = 0; nf < NF; nf++) {
            int nc = warp_n * WN + nf * 8 + tig * 2;
            if (p0) {
                __half2 hv = __floats2half2_rn(acc[mf][nf][0] * d0, acc[mf][nf][1] * d0);
                *(__half2*)&g_h16[(size_t)r0 * BN + nc] = hv;
            }
            if (p1) {
                __half2 hv = __floats2half2_rn(acc[mf][nf][2] * d1, acc[mf][nf][3] * d1);
                *(__half2*)&g_h16[(size_t)r1 * BN + nc] = hv;
            }
        }
    }
}

// ---------------- CSR aggregate, DIM=128: 16 lanes/node, uint4 gathers, 8-deep MLP -------
#define ACC8(U)  do {                                                   \
    float2 _p;                                                          \
    _p = __half22float2(*(const __half2*)&(U).x); a0 += _p.x; a1 += _p.y; \
    _p = __half22float2(*(const __half2*)&(U).y); a2 += _p.x; a3 += _p.y; \
    _p = __half22float2(*(const __half2*)&(U).z); a4 += _p.x; a5 += _p.y; \
    _p = __half22float2(*(const __half2*)&(U).w); a6 += _p.x; a7 += _p.y; \
} while (0)

template <bool RELU>
__global__ __launch_bounds__(256) void agg128_kernel(const float* __restrict__ b)
{
    int gt = blockIdx.x * 256 + threadIdx.x;
    int c = gt >> 4;               // 16 lanes per node
    int sl = threadIdx.x & 15;     // features 8*sl .. 8*sl+7
    if (c >= N_NODES) return;

    const uint4* hs = (const uint4*)g_h16;   // 16 uint4 per 128-dim row

    uint4 u = hs[(size_t)c * 16 + sl];
    float a0, a1, a2, a3, a4, a5, a6, a7;
    {
        float2 p;
        p = __half22float2(*(const __half2*)&u.x); a0 = p.x; a1 = p.y;
        p = __half22float2(*(const __half2*)&u.y); a2 = p.x; a3 = p.y;
        p = __half22float2(*(const __half2*)&u.z); a4 = p.x; a5 = p.y;
        p = __half22float2(*(const __half2*)&u.w); a6 = p.x; a7 = p.y;
    }

    int s = g_off[c], e = g_off[c + 1];
    int i = s;
    for (; i + 8 <= e; i += 8) {
        int r0 = g_adj[i],     r1 = g_adj[i + 1], r2 = g_adj[i + 2], r3 = g_adj[i + 3];
        int r4 = g_adj[i + 4], r5 = g_adj[i + 5], r6 = g_adj[i + 6], r7 = g_adj[i + 7];
        uint4 u0 = hs[(size_t)r0 * 16 + sl];
        uint4 u1 = hs[(size_t)r1 * 16 + sl];
        uint4 u2 = hs[(size_t)r2 * 16 + sl];
        uint4 u3 = hs[(size_t)r3 * 16 + sl];
        uint4 u4 = hs[(size_t)r4 * 16 + sl];
        uint4 u5 = hs[(size_t)r5 * 16 + sl];
        uint4 u6 = hs[(size_t)r6 * 16 + sl];
        uint4 u7 = hs[(size_t)r7 * 16 + sl];
        ACC8(u0); ACC8(u1); ACC8(u2); ACC8(u3);
        ACC8(u4); ACC8(u5); ACC8(u6); ACC8(u7);
    }
    for (; i < e; i++) {
        uint4 uv = hs[(size_t)g_adj[i] * 16 + sl];
        ACC8(uv);
    }

    float d = g_dinv[c];
    const float4* b4 = (const float4*)b;
    float4 bb0 = b4[sl * 2], bb1 = b4[sl * 2 + 1];
    float v0 = a0 * d + bb0.x, v1 = a1 * d + bb0.y;
    float v2 = a2 * d + bb0.z, v3 = a3 * d + bb0.w;
    float v4 = a4 * d + bb1.x, v5 = a5 * d + bb1.y;
    float v6 = a6 * d + bb1.z, v7 = a7 * d + bb1.w;
    if (RELU) {
        v0 = fmaxf(v0, 0.0f); v1 = fmaxf(v1, 0.0f);
        v2 = fmaxf(v2, 0.0f); v3 = fmaxf(v3, 0.0f);
        v4 = fmaxf(v4, 0.0f); v5 = fmaxf(v5, 0.0f);
        v6 = fmaxf(v6, 0.0f); v7 = fmaxf(v7, 0.0f);
    }
    __half2 h0 = __floats2half2_rn(v0, v1);
    __half2 h1 = __floats2half2_rn(v2, v3);
    __half2 h2 = __floats2half2_rn(v4, v5);
    __half2 h3 = __floats2half2_rn(v6, v7);
    uint4 w;
    w.x = *(unsigned*)&h0;  w.y = *(unsigned*)&h1;
    w.z = *(unsigned*)&h2;  w.w = *(unsigned*)&h3;
    ((uint4*)g_o16)[(size_t)c * 16 + sl] = w;
}

// DIM=64 final layer: 8 lanes per node, 8-deep MLP, writes d_out fp32.
__global__ __launch_bounds__(256) void agg64_kernel(float* __restrict__ out,
                                                    const float* __restrict__ b)
{
    int gt = blockIdx.x * 256 + threadIdx.x;
    int c = gt >> 3;               // 8 lanes per node
    int sl = threadIdx.x & 7;      // features 8*sl .. 8*sl+7
    if (c >= N_NODES) return;

    const uint4* hs = (const uint4*)g_h16;   // 8 uint4 per 64-dim row

    uint4 u = hs[(size_t)c * 8 + sl];
    float a0, a1, a2, a3, a4, a5, a6, a7;
    {
        float2 p;
        p = __half22float2(*(const __half2*)&u.x); a0 = p.x; a1 = p.y;
        p = __half22float2(*(const __half2*)&u.y); a2 = p.x; a3 = p.y;
        p = __half22float2(*(const __half2*)&u.z); a4 = p.x; a5 = p.y;
        p = __half22float2(*(const __half2*)&u.w); a6 = p.x; a7 = p.y;
    }

    int s = g_off[c], e = g_off[c + 1];
    int i = s;
    for (; i + 8 <= e; i += 8) {
        int r0 = g_adj[i],     r1 = g_adj[i + 1], r2 = g_adj[i + 2], r3 = g_adj[i + 3];
        int r4 = g_adj[i + 4], r5 = g_adj[i + 5], r6 = g_adj[i + 6], r7 = g_adj[i + 7];
        uint4 u0 = hs[(size_t)r0 * 8 + sl];
        uint4 u1 = hs[(size_t)r1 * 8 + sl];
        uint4 u2 = hs[(size_t)r2 * 8 + sl];
        uint4 u3 = hs[(size_t)r3 * 8 + sl];
        uint4 u4 = hs[(size_t)r4 * 8 + sl];
        uint4 u5 = hs[(size_t)r5 * 8 + sl];
        uint4 u6 = hs[(size_t)r6 * 8 + sl];
        uint4 u7 = hs[(size_t)r7 * 8 + sl];
        ACC8(u0); ACC8(u1); ACC8(u2); ACC8(u3);
        ACC8(u4); ACC8(u5); ACC8(u6); ACC8(u7);
    }
    for (; i < e; i++) {
        uint4 uv = hs[(size_t)g_adj[i] * 8 + sl];
        ACC8(uv);
    }

    float d = g_dinv[c];
    const float4* b4 = (const float4*)b;
    float4 bb0 = b4[sl * 2], bb1 = b4[sl * 2 + 1];
    float4 r0v, r1v;
    r0v.x = a0 * d + bb0.x;  r0v.y = a1 * d + bb0.y;
    r0v.z = a2 * d + bb0.z;  r0v.w = a3 * d + bb0.w;
    r1v.x = a4 * d + bb1.x;  r1v.y = a5 * d + bb1.y;
    r1v.z = a6 * d + bb1.z;  r1v.w = a7 * d + bb1.w;
    float4* o4 = (float4*)out;
    o4[(size_t)c * 16 + sl * 2]     = r0v;
    o4[(size_t)c * 16 + sl * 2 + 1] = r1v;
}

// ---------------- launch ----------------
extern "C" void kernel_launch(void* const* d_in, const int* in_sizes, int n_in,
                              void* d_out, int out_size)
{
    const float* x      = (const float*)d_in[0];
    const int*   ei_raw = (const int*)d_in[1];
    const float* W1 = (const float*)d_in[2];
    const float* b1 = (const float*)d_in[3];
    const float* W2 = (const float*)d_in[4];
    const float* b2 = (const float*)d_in[5];
    const float* W3 = (const float*)d_in[6];
    const float* b3 = (const float*)d_in[7];
    float* out = (float*)d_out;

    // side stream + events, created once on the uncaptured correctness call
    static cudaStream_t s2 = nullptr;
    static cudaEvent_t  eA = nullptr, eB = nullptr;
    if (s2 == nullptr) {
        cudaStreamCreateWithFlags(&s2, cudaStreamNonBlocking);
        cudaEventCreateWithFlags(&eA, cudaEventDisableTiming);
        cudaEventCreateWithFlags(&eB, cudaEventDisableTiming);
    }

    const int gemmRows = (N_NODES + 127) / 128;               // 391
    const int agg128Grid = (N_NODES * 16 + 255) / 256;        // 16 lanes/node
    const int agg64Grid  = (N_NODES * 8 + 255) / 256;         // 8 lanes/node

    // ---- preamble: dtype + degrees + dinv (gemm1 dependency) ----
    detect_zero_kernel<<<NB, 256>>>(ei_raw);
    count_kernel<<<(N_EDGES + 255) / 256, 256>>>(ei_raw);
    dinv_kernel<<<NB, 256>>>();

    // fork: gemm1 on s2 overlaps scan/fill chain on main stream
    cudaEventRecord(eA, 0);
    cudaStreamWaitEvent(s2, eA, 0);
    gemm_tc_kernel<128, 0><<<dim3(1, gemmRows), 256, 0, s2>>>(x, W1);

    scanA_kernel<<<NB, 256>>>();
    scanBC_kernel<<<NB, 256>>>();
    fill_kernel<<<(N_EDGES + 255) / 256, 256>>>(ei_raw);

    cudaEventRecord(eB, s2);
    cudaStreamWaitEvent(0, eB, 0);

    // ---- layer 1 aggregate ----
    agg128_kernel<true><<<agg128Grid, 256>>>(b1);

    // ---- layer 2 ----
    gemm_tc_kernel<128, 1><<<dim3(1, gemmRows), 256>>>(nullptr, W2);
    agg128_kernel<true><<<agg128Grid, 256>>>(b2);

    // ---- layer 3 (dim 64 -> d_out) ----
    gemm_tc_kernel<64, 1><<<dim3(1, gemmRows), 256>>>(nullptr, W3);
    agg64_kernel<<<agg64Grid, 256>>>(out, b3);
}

// round 15
// speedup vs baseline: 4.0503x; 1.1354x over previous
#include <cuda_runtime.h>
#include <cuda_fp16.h>
#include <stdint.h>

#define N_NODES 50000
#define N_EDGES 800000
#define NB      208            // scan blocks: 208*256 = 53248 >= N_NODES

// ---------------- scratch (allocation-free: __device__ globals) ----------------
__device__ __align__(16) float  g_dinv[N_NODES];
__device__ __align__(16) __half g_h16[N_NODES * 128]; // GEMM out, dinv-prescaled, fp16
__device__ __align__(16) __half g_o16[N_NODES * 128]; // layer output (fp16, next GEMM A)
__device__ __align__(16) __half g_w1t[128 * 128];     // W1^T fp16 (n-major rows of 128)
__device__ __align__(16) __half g_w2t[128 * 128];     // W2^T fp16
__device__ __align__(16) __half g_w3t[64 * 128];      // W3^T fp16
__device__ int g_adj[N_EDGES];
__device__ int g_off[N_NODES + 1];
__device__ int g_cur[N_NODES];
__device__ int g_degi[N_NODES];
__device__ int g_bsum[NB];
__device__ int g_is64;

// ---------------- detect dtype + zero degrees (one launch) ----------------
__global__ void detect_zero_kernel(const int* __restrict__ ei_raw) {
    int i = blockIdx.x * 256 + threadIdx.x;
    if (i < N_NODES) g_degi[i] = 0;
    if (blockIdx.x == 0) {
        __shared__ int any;
        if (threadIdx.x == 0) any = 0;
        __syncthreads();
        int nz = 0;
        for (int j = threadIdx.x; j < 1024; j += 256)
            nz |= ei_raw[2 * j + 1];
        if (nz) atomicOr(&any, 1);
        __syncthreads();
        if (threadIdx.x == 0) g_is64 = (any == 0);
    }
}

__global__ void count_kernel(const int* __restrict__ ei_raw) {
    int i = blockIdx.x * blockDim.x + threadIdx.x;
    if (i >= N_EDGES) return;
    int c = g_is64 ? ei_raw[2 * (N_EDGES + i)] : ei_raw[N_EDGES + i];
    atomicAdd(&g_degi[c], 1);
}

__global__ void dinv_kernel() {
    int i = blockIdx.x * 256 + threadIdx.x;
    if (i < N_NODES) g_dinv[i] = rsqrtf((float)(1 + g_degi[i]));
}

// ---------------- weight transpose to fp16 n-major: out[n][k] = W[k][n] -------
template <int WID, int N>   // WID selects destination buffer
__global__ void wt_kernel(const float* __restrict__ W) {
    __half* outp = (WID == 1) ? g_w1t : (WID == 2) ? g_w2t : g_w3t;
    int idx = blockIdx.x * 256 + threadIdx.x;
    if (idx >= 128 * N) return;
    int n = idx % N;
    int k = idx / N;
    outp[n * 128 + k] = __float2half(W[(size_t)k * N + n]);
}

// ---------------- scan phase A: per-block degree sums ----------------
__global__ __launch_bounds__(256) void scanA_kernel() {
    __shared__ int sh[256];
    int i = blockIdx.x * 256 + threadIdx.x;
    int v = (i < N_NODES) ? g_degi[i] : 0;
    sh[threadIdx.x] = v;
    __syncthreads();
    for (int o = 128; o > 0; o >>= 1) {
        if (threadIdx.x < o) sh[threadIdx.x] += sh[threadIdx.x + o];
        __syncthreads();
    }
    if (threadIdx.x == 0) g_bsum[blockIdx.x] = sh[0];
}

// ---------------- scan phase B+C merged: offsets + cursors ----------------
__global__ __launch_bounds__(256) void scanBC_kernel() {
    __shared__ int pre[256];
    __shared__ int sh[256];
    int t = threadIdx.x;

    pre[t] = (t < NB && t < blockIdx.x) ? g_bsum[t] : 0;
    __syncthreads();
    for (int o = 128; o > 0; o >>= 1) {
        if (t < o) pre[t] += pre[t + o];
        __syncthreads();
    }
    int bpref = pre[0];

    int i = blockIdx.x * 256 + t;
    int d = (i < N_NODES) ? g_degi[i] : 0;
    sh[t] = d;
    __syncthreads();
    for (int o = 1; o < 256; o <<= 1) {
        int x = sh[t];
        int a = (t >= o) ? sh[t - o] : 0;
        __syncthreads();
        sh[t] = x + a;
        __syncthreads();
    }
    if (i < N_NODES) {
        int excl = sh[t] - d + bpref;
        g_off[i] = excl;
        g_cur[i] = excl;
    }
    if (i == 0) g_off[N_NODES] = N_EDGES;
}

__global__ void fill_kernel(const int* __restrict__ ei_raw) {
    int i = blockIdx.x * blockDim.x + threadIdx.x;
    if (i >= N_EDGES) return;
    int r, c;
    if (g_is64) {
        r = ei_raw[2 * i];
        c = ei_raw[2 * (N_EDGES + i)];
    } else {
        r = ei_raw[i];
        c = ei_raw[N_EDGES + i];
    }
    int pos = atomicAdd(&g_cur[c], 1);
    g_adj[pos] = r;
}

// ---------------- fp16 GEMM, full-K single-stage: g_h16 = fp16(dinv*(A@B)) ----------
// Block tile 128 x BN, 8 warps (2M x 4N). Entire K=128 staged once; one sync;
// 8 sync-free mma k-steps. Row stride 136 halfs (68 words): frag-load patterns
// hit all 32 banks. Dynamic smem (52-70KB), attribute set in init.
#define LDK 136   // padded row length in halfs

template <int BN, int SRC, int WID>   // SRC=0: A=Aext fp32; SRC=1: A=g_o16 fp16
__global__ __launch_bounds__(256, 2) void gemm_tc_kernel(
    const float* __restrict__ Aext)
{
    constexpr int WN = BN / 4;
    constexpr int NF = WN / 8;

    extern __shared__ __half sm[];
    __half* Ah = sm;                    // [128][LDK]
    __half* Bh = sm + 128 * LDK;        // [BN][LDK]

    const __half* Bt = (WID == 1) ? g_w1t : (WID == 2) ? g_w2t : g_w3t;

    int tid  = threadIdx.x;
    int warp = tid >> 5;
    int lane = tid & 31;
    int gid  = lane >> 2;
    int tig  = lane & 3;
    int warp_m = warp >> 2;
    int warp_n = warp & 3;
    int rowBase = blockIdx.y * 128;

    // ---- stage A: 128 rows x 128 halfs ----
    if (SRC == 0) {
        // fp32 -> fp16 convert; 64 half2 per row; 256 threads, 32 iters
#pragma unroll
        for (int i = 0; i < 32; i++) {
            int idx = tid + i * 256;           // 0..8191 half2
            int m  = idx >> 6;                  // /64
            int k2 = idx & 63;
            int gm = rowBase + m;
            float2 v = (gm < N_NODES)
                ? *(const float2*)&Aext[(size_t)gm * 128 + 2 * k2]
                : make_float2(0.0f, 0.0f);
            *(__half2*)&Ah[m * LDK + 2 * k2] = __float22half2_rn(v);
        }
    } else {
        // raw fp16 copy; 16 uint4 per row; 256 threads, 8 iters
#pragma unroll
        for (int i = 0; i < 8; i++) {
            int idx = tid + i * 256;           // 0..2047 uint4
            int m = idx >> 4;
            int j = idx & 15;
            int gm = rowBase + m;
            uint4 v = (gm < N_NODES)
                ? *(const uint4*)&g_o16[(size_t)gm * 128 + 8 * j]
                : make_uint4(0, 0, 0, 0);
            *(uint4*)&Ah[m * LDK + 8 * j] = v;
        }
    }
    // ---- stage B: BN rows x 128 halfs from pre-transposed fp16 ----
#pragma unroll
    for (int i = 0; i < (BN * 16) / 256; i++) {
        int idx = tid + i * 256;
        int n = idx >> 4;
        int j = idx & 15;
        uint4 v = *(const uint4*)&Bt[n * 128 + 8 * j];
        *(uint4*)&Bh[n * LDK + 8 * j] = v;
    }
    __syncthreads();

    float acc[4][NF][4];
#pragma unroll
    for (int mf = 0; mf < 4; mf++)
#pragma unroll
        for (int nf = 0; nf < NF; nf++)
#pragma unroll
            for (int q = 0; q < 4; q++) acc[mf][nf][q] = 0.0f;

#pragma unroll
    for (int ks = 0; ks < 8; ks++) {
        int k0 = ks * 16;
        unsigned a[4][4];
#pragma unroll
        for (int mf = 0; mf < 4; mf++) {
            int rb = warp_m * 64 + mf * 16;
            a[mf][0] = *(const unsigned*)&Ah[(rb + gid) * LDK + k0 + 2 * tig];
            a[mf][1] = *(const unsigned*)&Ah[(rb + gid + 8) * LDK + k0 + 2 * tig];
            a[mf][2] = *(const unsigned*)&Ah[(rb + gid) * LDK + k0 + 2 * tig + 8];
            a[mf][3] = *(const unsigned*)&Ah[(rb + gid + 8) * LDK + k0 + 2 * tig + 8];
        }
#pragma unroll
        for (int nf = 0; nf < NF; nf++) {
            int nb = warp_n * WN + nf * 8;
            unsigned b0 = *(const unsigned*)&Bh[(nb + gid) * LDK + k0 + 2 * tig];
            unsigned b1 = *(const unsigned*)&Bh[(nb + gid) * LDK + k0 + 2 * tig + 8];
#pragma unroll
            for (int mf = 0; mf < 4; mf++) {
                asm volatile(
                    "mma.sync.aligned.m16n8k16.row.col.f32.f16.f16.f32 "
                    "{%0,%1,%2,%3}, {%4,%5,%6,%7}, {%8,%9}, {%0,%1,%2,%3};"
                    : "+f"(acc[mf][nf][0]), "+f"(acc[mf][nf][1]),
                      "+f"(acc[mf][nf][2]), "+f"(acc[mf][nf][3])
                    : "r"(a[mf][0]), "r"(a[mf][1]),
                      "r"(a[mf][2]), "r"(a[mf][3]),
                      "r"(b0), "r"(b1));
            }
        }
    }

    // epilogue: scale rows by dinv, pack to half2, store to g_h16
#pragma unroll
    for (int mf = 0; mf < 4; mf++) {
        int r0 = rowBase + warp_m * 64 + mf * 16 + gid;
        int r1 = r0 + 8;
        bool p0 = (r0 < N_NODES);
        bool p1 = (r1 < N_NODES);
        float d0 = p0 ? g_dinv[r0] : 0.0f;
        float d1 = p1 ? g_dinv[r1] : 0.0f;
#pragma unroll
        for (int nf = 0; nf < NF; nf++) {
            int nc = warp_n * WN + nf * 8 + tig * 2;
            if (p0) {
                __half2 hv = __floats2half2_rn(acc[mf][nf][0] * d0, acc[mf][nf][1] * d0);
                *(__half2*)&g_h16[(size_t)r0 * BN + nc] = hv;
            }
            if (p1) {
                __half2 hv = __floats2half2_rn(acc[mf][nf][2] * d1, acc[mf][nf][3] * d1);
                *(__half2*)&g_h16[(size_t)r1 * BN + nc] = hv;
            }
        }
    }
}

// ---------------- CSR aggregate, DIM=128: 16 lanes/node, uint4 gathers, 8-deep MLP -------
#define ACC8(U)  do {                                                   \
    float2 _p;                                                          \
    _p = __half22float2(*(const __half2*)&(U).x); a0 += _p.x; a1 += _p.y; \
    _p = __half22float2(*(const __half2*)&(U).y); a2 += _p.x; a3 += _p.y; \
    _p = __half22float2(*(const __half2*)&(U).z); a4 += _p.x; a5 += _p.y; \
    _p = __half22float2(*(const __half2*)&(U).w); a6 += _p.x; a7 += _p.y; \
} while (0)

template <bool RELU>
__global__ __launch_bounds__(256) void agg128_kernel(const float* __restrict__ b)
{
    int gt = blockIdx.x * 256 + threadIdx.x;
    int c = gt >> 4;
    int sl = threadIdx.x & 15;
    if (c >= N_NODES) return;

    const uint4* hs = (const uint4*)g_h16;

    uint4 u = hs[(size_t)c * 16 + sl];
    float a0, a1, a2, a3, a4, a5, a6, a7;
    {
        float2 p;
        p = __half22float2(*(const __half2*)&u.x); a0 = p.x; a1 = p.y;
        p = __half22float2(*(const __half2*)&u.y); a2 = p.x; a3 = p.y;
        p = __half22float2(*(const __half2*)&u.z); a4 = p.x; a5 = p.y;
        p = __half22float2(*(const __half2*)&u.w); a6 = p.x; a7 = p.y;
    }

    int s = g_off[c], e = g_off[c + 1];
    int i = s;
    for (; i + 8 <= e; i += 8) {
        int r0 = g_adj[i],     r1 = g_adj[i + 1], r2 = g_adj[i + 2], r3 = g_adj[i + 3];
        int r4 = g_adj[i + 4], r5 = g_adj[i + 5], r6 = g_adj[i + 6], r7 = g_adj[i + 7];
        uint4 u0 = hs[(size_t)r0 * 16 + sl];
        uint4 u1 = hs[(size_t)r1 * 16 + sl];
        uint4 u2 = hs[(size_t)r2 * 16 + sl];
        uint4 u3 = hs[(size_t)r3 * 16 + sl];
        uint4 u4 = hs[(size_t)r4 * 16 + sl];
        uint4 u5 = hs[(size_t)r5 * 16 + sl];
        uint4 u6 = hs[(size_t)r6 * 16 + sl];
        uint4 u7 = hs[(size_t)r7 * 16 + sl];
        ACC8(u0); ACC8(u1); ACC8(u2); ACC8(u3);
        ACC8(u4); ACC8(u5); ACC8(u6); ACC8(u7);
    }
    for (; i < e; i++) {
        uint4 uv = hs[(size_t)g_adj[i] * 16 + sl];
        ACC8(uv);
    }

    float d = g_dinv[c];
    const float4* b4 = (const float4*)b;
    float4 bb0 = b4[sl * 2], bb1 = b4[sl * 2 + 1];
    float v0 = a0 * d + bb0.x, v1 = a1 * d + bb0.y;
    float v2 = a2 * d + bb0.z, v3 = a3 * d + bb0.w;
    float v4 = a4 * d + bb1.x, v5 = a5 * d + bb1.y;
    float v6 = a6 * d + bb1.z, v7 = a7 * d + bb1.w;
    if (RELU) {
        v0 = fmaxf(v0, 0.0f); v1 = fmaxf(v1, 0.0f);
        v2 = fmaxf(v2, 0.0f); v3 = fmaxf(v3, 0.0f);
        v4 = fmaxf(v4, 0.0f); v5 = fmaxf(v5, 0.0f);
        v6 = fmaxf(v6, 0.0f); v7 = fmaxf(v7, 0.0f);
    }
    __half2 h0 = __floats2half2_rn(v0, v1);
    __half2 h1 = __floats2half2_rn(v2, v3);
    __half2 h2 = __floats2half2_rn(v4, v5);
    __half2 h3 = __floats2half2_rn(v6, v7);
    uint4 w;
    w.x = *(unsigned*)&h0;  w.y = *(unsigned*)&h1;
    w.z = *(unsigned*)&h2;  w.w = *(unsigned*)&h3;
    ((uint4*)g_o16)[(size_t)c * 16 + sl] = w;
}

// DIM=64 final layer: 8 lanes per node, 8-deep MLP, writes d_out fp32.
__global__ __launch_bounds__(256) void agg64_kernel(float* __restrict__ out,
                                                    const float* __restrict__ b)
{
    int gt = blockIdx.x * 256 + threadIdx.x;
    int c = gt >> 3;
    int sl = threadIdx.x & 7;
    if (c >= N_NODES) return;

    const uint4* hs = (const uint4*)g_h16;

    uint4 u = hs[(size_t)c * 8 + sl];
    float a0, a1, a2, a3, a4, a5, a6, a7;
    {
        float2 p;
        p = __half22float2(*(const __half2*)&u.x); a0 = p.x; a1 = p.y;
        p = __half22float2(*(const __half2*)&u.y); a2 = p.x; a3 = p.y;
        p = __half22float2(*(const __half2*)&u.z); a4 = p.x; a5 = p.y;
        p = __half22float2(*(const __half2*)&u.w); a6 = p.x; a7 = p.y;
    }

    int s = g_off[c], e = g_off[c + 1];
    int i = s;
    for (; i + 8 <= e; i += 8) {
        int r0 = g_adj[i],     r1 = g_adj[i + 1], r2 = g_adj[i + 2], r3 = g_adj[i + 3];
        int r4 = g_adj[i + 4], r5 = g_adj[i + 5], r6 = g_adj[i + 6], r7 = g_adj[i + 7];
        uint4 u0 = hs[(size_t)r0 * 8 + sl];
        uint4 u1 = hs[(size_t)r1 * 8 + sl];
        uint4 u2 = hs[(size_t)r2 * 8 + sl];
        uint4 u3 = hs[(size_t)r3 * 8 + sl];
        uint4 u4 = hs[(size_t)r4 * 8 + sl];
        uint4 u5 = hs[(size_t)r5 * 8 + sl];
        uint4 u6 = hs[(size_t)r6 * 8 + sl];
        uint4 u7 = hs[(size_t)r7 * 8 + sl];
        ACC8(u0); ACC8(u1); ACC8(u2); ACC8(u3);
        ACC8(u4); ACC8(u5); ACC8(u6); ACC8(u7);
    }
    for (; i < e; i++) {
        uint4 uv = hs[(size_t)g_adj[i] * 8 + sl];
        ACC8(uv);
    }

    float d = g_dinv[c];
    const float4* b4 = (const float4*)b;
    float4 bb0 = b4[sl * 2], bb1 = b4[sl * 2 + 1];
    float4 r0v, r1v;
    r0v.x = a0 * d + bb0.x;  r0v.y = a1 * d + bb0.y;
    r0v.z = a2 * d + bb0.z;  r0v.w = a3 * d + bb0.w;
    r1v.x = a4 * d + bb1.x;  r1v.y = a5 * d + bb1.y;
    r1v.z = a6 * d + bb1.z;  r1v.w = a7 * d + bb1.w;
    float4* o4 = (float4*)out;
    o4[(size_t)c * 16 + sl * 2]     = r0v;
    o4[(size_t)c * 16 + sl * 2 + 1] = r1v;
}

// ---------------- launch ----------------
extern "C" void kernel_launch(void* const* d_in, const int* in_sizes, int n_in,
                              void* d_out, int out_size)
{
    const float* x      = (const float*)d_in[0];
    const int*   ei_raw = (const int*)d_in[1];
    const float* W1 = (const float*)d_in[2];
    const float* b1 = (const float*)d_in[3];
    const float* W2 = (const float*)d_in[4];
    const float* b2 = (const float*)d_in[5];
    const float* W3 = (const float*)d_in[6];
    const float* b3 = (const float*)d_in[7];
    float* out = (float*)d_out;

    constexpr int SMEM128 = (128 + 128) * LDK * 2;   // 69,632 B
    constexpr int SMEM64  = (128 + 64)  * LDK * 2;   // 52,224 B

    // one-time init on the uncaptured correctness call: stream, events, smem attrs
    static cudaStream_t s2 = nullptr;
    static cudaEvent_t  eA = nullptr, eB = nullptr;
    if (s2 == nullptr) {
        cudaStreamCreateWithFlags(&s2, cudaStreamNonBlocking);
        cudaEventCreateWithFlags(&eA, cudaEventDisableTiming);
        cudaEventCreateWithFlags(&eB, cudaEventDisableTiming);
        cudaFuncSetAttribute(gemm_tc_kernel<128, 0, 1>,
                             cudaFuncAttributeMaxDynamicSharedMemorySize, SMEM128);
        cudaFuncSetAttribute(gemm_tc_kernel<128, 1, 2>,
                             cudaFuncAttributeMaxDynamicSharedMemorySize, SMEM128);
        cudaFuncSetAttribute(gemm_tc_kernel<64, 1, 3>,
                             cudaFuncAttributeMaxDynamicSharedMemorySize, SMEM64);
    }

    const int gemmRows = (N_NODES + 127) / 128;               // 391
    const int agg128Grid = (N_NODES * 16 + 255) / 256;
    const int agg64Grid  = (N_NODES * 8 + 255) / 256;

    // ---- preamble: dtype + degrees + dinv (gemm1 dependency) ----
    detect_zero_kernel<<<NB, 256>>>(ei_raw);
    count_kernel<<<(N_EDGES + 255) / 256, 256>>>(ei_raw);
    dinv_kernel<<<NB, 256>>>();

    // fork: wt1 + gemm1 on s2 overlap scan/fill chain on main stream
    cudaEventRecord(eA, 0);
    cudaStreamWaitEvent(s2, eA, 0);
    wt_kernel<1, 128><<<64, 256, 0, s2>>>(W1);
    gemm_tc_kernel<128, 0, 1><<<dim3(1, gemmRows), 256, SMEM128, s2>>>(x);

    scanA_kernel<<<NB, 256>>>();
    scanBC_kernel<<<NB, 256>>>();
    fill_kernel<<<(N_EDGES + 255) / 256, 256>>>(ei_raw);
    wt_kernel<2, 128><<<64, 256>>>(W2);
    wt_kernel<3, 64><<<32, 256>>>(W3);

    cudaEventRecord(eB, s2);
    cudaStreamWaitEvent(0, eB, 0);

    // ---- layer 1 aggregate ----
    agg128_kernel<true><<<agg128Grid, 256>>>(b1);

    // ---- layer 2 ----
    gemm_tc_kernel<128, 1, 2><<<dim3(1, gemmRows), 256, SMEM128>>>(nullptr);
    agg128_kernel<true><<<agg128Grid, 256>>>(b2);

    // ---- layer 3 (dim 64 -> d_out) ----
    gemm_tc_kernel<64, 1, 3><<<dim3(1, gemmRows), 256, SMEM64>>>(nullptr);
    agg64_kernel<<<agg64Grid, 256>>>(out, b3);
}